// round 1
// baseline (speedup 1.0000x reference)
#include <cuda_runtime.h>
#include <math.h>

// ---------------- static device scratch (no runtime allocation) ----------------
__device__ __align__(16) float g_X[2*512*1024];      // embedded inputs, both trees
__device__ __align__(16) float g_XIOU[2*512*3072];   // x @ w_ioux^T + b_ioux
__device__ __align__(16) float g_XF[2*512*1024];     // x @ w_fx^T + b_fx
__device__ __align__(16) float g_H[2*512*1024];      // hidden states by rank
__device__ __align__(16) float g_C[2*512*1024];      // cell states by rank
__device__ __align__(16) float g_IOU[256*3072];      // per-level hsum @ w_iouh^T
__device__ __align__(16) float g_FP[512*1024];       // per-level ch @ w_fh^T
__device__ __align__(16) float g_HB[1024*256];       // tanh(H @ ws1^T)
__device__ __align__(16) float g_LOG[1024*16];       // hbar @ ws2^T
__device__ __align__(16) float g_ALPHA[2*16*512];    // softmax attention
__device__ __align__(16) float g_Mm[32*1024];        // alphas @ H
__device__ __align__(16) float g_LS[32*1024];        // relu(M @ wf)
__device__ __align__(16) float g_FR[3072];
__device__ __align__(16) float g_FC[512];
__device__ __align__(16) float g_FC2[256];

struct LvlArg  { int r[128]; };
struct LeafArg { int r[256]; };

__device__ __forceinline__ float sigm(float x){ return 1.f/(1.f+expf(-x)); }

// ---------------- generic fp32 GEMM: C[M,N] = act(A @ op(B) + bias) ----------------
// AMODE 0: plain A (lda=K)
// AMODE 1: A row i -> masked sum of two child H rows (i = t*Bn + j), A = g_H base
// AMODE 2: A row i -> single masked child H row (i = t*2Bn + 2j + ck), A = g_H base
// BT true: B is [N,K] row-major (C = A@B^T); false: B is [K,N] row-major (C = A@B)
// ACT 0 none, 1 tanh, 2 relu
template<int AMODE, bool BT, int ACT>
__global__ void gemm64(const float* __restrict__ A, const float* __restrict__ B,
                       const float* __restrict__ bias, float* __restrict__ C,
                       int M, int N, int K,
                       const int* __restrict__ cidx, const float* __restrict__ cmask,
                       LvlArg lvl, int Bn)
{
    __shared__ float As[16][72];
    __shared__ float Bs[16][72];
    int tid = threadIdx.x;
    int rowBase = blockIdx.y*64, colBase = blockIdx.x*64;
    int tx = tid & 15, ty = tid >> 4;
    int aRow = tid >> 2, aK4 = (tid & 3)*4;

    float acc[4][4];
    #pragma unroll
    for (int i=0;i<4;i++)
        #pragma unroll
        for (int j=0;j<4;j++) acc[i][j] = 0.f;

    for (int k0=0; k0<K; k0+=16) {
        // ---- A tile ----
        float4 av = make_float4(0.f,0.f,0.f,0.f);
        int gr = rowBase + aRow;
        if (gr < M) {
            if (AMODE == 0) {
                av = *(const float4*)(A + (size_t)gr*K + k0 + aK4);
            } else if (AMODE == 1) {
                int t = gr / Bn, j = gr - t*Bn;
                int r = lvl.r[j];
                int c0 = cidx[2*r], c1 = cidx[2*r+1];
                float m0 = cmask[2*r], m1 = cmask[2*r+1];
                float4 h0 = *(const float4*)(A + ((size_t)(t*512 + c0))*1024 + k0 + aK4);
                float4 h1 = *(const float4*)(A + ((size_t)(t*512 + c1))*1024 + k0 + aK4);
                av.x = h0.x*m0 + h1.x*m1;
                av.y = h0.y*m0 + h1.y*m1;
                av.z = h0.z*m0 + h1.z*m1;
                av.w = h0.w*m0 + h1.w*m1;
            } else {
                int t = gr / (2*Bn), rem = gr - t*2*Bn, j = rem >> 1, ck = rem & 1;
                int r = lvl.r[j];
                int c = cidx[2*r+ck]; float mk = cmask[2*r+ck];
                float4 h = *(const float4*)(A + ((size_t)(t*512 + c))*1024 + k0 + aK4);
                av.x = h.x*mk; av.y = h.y*mk; av.z = h.z*mk; av.w = h.w*mk;
            }
        }
        As[aK4+0][aRow]=av.x; As[aK4+1][aRow]=av.y;
        As[aK4+2][aRow]=av.z; As[aK4+3][aRow]=av.w;

        // ---- B tile ----
        if (BT) {
            float4 bv = make_float4(0.f,0.f,0.f,0.f);
            int gn = colBase + aRow;
            if (gn < N) bv = *(const float4*)(B + (size_t)gn*K + k0 + aK4);
            Bs[aK4+0][aRow]=bv.x; Bs[aK4+1][aRow]=bv.y;
            Bs[aK4+2][aRow]=bv.z; Bs[aK4+3][aRow]=bv.w;
        } else {
            int bK = tid >> 4, bN4 = (tid & 15)*4;
            float4 bv = *(const float4*)(B + (size_t)(k0+bK)*N + colBase + bN4);
            *(float4*)&Bs[bK][bN4] = bv;
        }
        __syncthreads();

        #pragma unroll
        for (int kk=0; kk<16; kk++) {
            float4 a4 = *(const float4*)(&As[kk][ty*4]);
            float4 b4 = *(const float4*)(&Bs[kk][tx*4]);
            float aa[4] = {a4.x,a4.y,a4.z,a4.w};
            float bb[4] = {b4.x,b4.y,b4.z,b4.w};
            #pragma unroll
            for (int i=0;i<4;i++)
                #pragma unroll
                for (int j=0;j<4;j++) acc[i][j] += aa[i]*bb[j];
        }
        __syncthreads();
    }

    #pragma unroll
    for (int i=0;i<4;i++) {
        int row = rowBase + ty*4 + i;
        if (row < M) {
            #pragma unroll
            for (int j=0;j<4;j++) {
                int col = colBase + tx*4 + j;
                if (col < N) {
                    float v = acc[i][j];
                    if (bias) v += bias[col];
                    if (ACT == 1) v = tanhf(v);
                    else if (ACT == 2) v = fmaxf(v, 0.f);
                    C[(size_t)row*N + col] = v;
                }
            }
        }
    }
}

// ---------------- pointwise kernels ----------------
__global__ void k_embed(const int* __restrict__ lin, const int* __restrict__ rin,
                        const float* __restrict__ emb)
{
    int row = blockIdx.x;               // 0..1023
    int t = row >> 9, n = row & 511;
    int tok = t ? rin[n] : lin[n];
    const float4* src = (const float4*)(emb + (size_t)tok*1024);
    float4* dst = (float4*)(g_X + (size_t)row*1024);
    dst[threadIdx.x] = src[threadIdx.x];
}

__global__ void k_leaf(LeafArg lf, const float* __restrict__ b_iouh)
{
    int gid = blockIdx.x*256 + threadIdx.x;   // 2*256*1024 total
    int i = gid >> 10, m = gid & 1023;
    int t = i >> 8, j = i & 255;
    int r = lf.r[j];
    size_t x = (size_t)(t*512 + r);
    float ig = g_XIOU[x*3072 + m]        + b_iouh[m];
    float og = g_XIOU[x*3072 + 1024 + m] + b_iouh[1024 + m];
    float ug = g_XIOU[x*3072 + 2048 + m] + b_iouh[2048 + m];
    float c = sigm(ig) * tanhf(ug);
    g_C[x*1024 + m] = c;
    g_H[x*1024 + m] = sigm(og) * tanhf(c);
}

__global__ void k_point(const int* __restrict__ cidx, const float* __restrict__ cmask,
                        LvlArg lvl, int Bn,
                        const float* __restrict__ b_iouh, const float* __restrict__ b_fh)
{
    int gid = blockIdx.x*256 + threadIdx.x;
    if (gid >= 2*Bn*1024) return;
    int i = gid >> 10, m = gid & 1023;
    int t = i / Bn, j = i - t*Bn;
    int r = lvl.r[j];
    size_t x = (size_t)(t*512 + r);
    float ig = g_XIOU[x*3072 + m]        + g_IOU[(size_t)i*3072 + m]        + b_iouh[m];
    float og = g_XIOU[x*3072 + 1024 + m] + g_IOU[(size_t)i*3072 + 1024 + m] + b_iouh[1024 + m];
    float ug = g_XIOU[x*3072 + 2048 + m] + g_IOU[(size_t)i*3072 + 2048 + m] + b_iouh[2048 + m];
    float xf = g_XF[x*1024 + m];
    float f0 = sigm(g_FP[(size_t)(2*i  )*1024 + m] + b_fh[m] + xf);
    float f1 = sigm(g_FP[(size_t)(2*i+1)*1024 + m] + b_fh[m] + xf);
    int c0 = cidx[2*r], c1 = cidx[2*r+1];
    float m0 = cmask[2*r], m1 = cmask[2*r+1];
    float cc0 = g_C[((size_t)(t*512 + c0))*1024 + m] * m0;
    float cc1 = g_C[((size_t)(t*512 + c1))*1024 + m] * m1;
    float c = sigm(ig)*tanhf(ug) + f0*cc0 + f1*cc1;
    g_C[x*1024 + m] = c;
    g_H[x*1024 + m] = sigm(og)*tanhf(c);
}

__global__ void k_soft(float* __restrict__ out)
{
    __shared__ float sh[512];
    int b = blockIdx.x;                 // t*16 + hop
    int t = b >> 4, hop = b & 15;
    int n = threadIdx.x;                // 512 threads
    float v = g_LOG[(size_t)(t*512 + n)*16 + hop];
    sh[n] = v; __syncthreads();
    for (int s=256; s>0; s>>=1){ if (n < s) sh[n] = fmaxf(sh[n], sh[n+s]); __syncthreads(); }
    float mx = sh[0]; __syncthreads();
    float e = expf(v - mx);
    sh[n] = e; __syncthreads();
    for (int s=256; s>0; s>>=1){ if (n < s) sh[n] += sh[n+s]; __syncthreads(); }
    float a = e / sh[0];
    g_ALPHA[(size_t)b*512 + n] = a;
    out[5 + t*8192 + hop*512 + n] = a;
}

__global__ void k_lat(const float* __restrict__ w_lat, const float* __restrict__ b_lat)
{
    int m = blockIdx.x*256 + threadIdx.x;   // 1024
    float lv = b_lat[0], rv = b_lat[0];
    #pragma unroll
    for (int h=0; h<16; h++) {
        float w = w_lat[h];
        lv += w * g_LS[h*1024 + m];
        rv += w * g_LS[(16 + h)*1024 + m];
    }
    g_FR[m]        = fabsf(lv - rv);
    g_FR[1024 + m] = lv * rv;
    g_FR[2048 + m] = 0.5f * (lv + rv);
}

__global__ void k_fc(const float* __restrict__ w, const float* __restrict__ bb)
{
    int o = blockIdx.x*8 + (threadIdx.x >> 5);
    int lane = threadIdx.x & 31;
    const float* wr = w + (size_t)o*3072;
    float s = 0.f;
    for (int k=lane; k<3072; k+=32) s += g_FR[k]*wr[k];
    for (int d=16; d; d>>=1) s += __shfl_down_sync(0xffffffffu, s, d);
    if (!lane) { float v = s + bb[o]; g_FC[o] = v > 0.f ? v : 0.01f*v; }
}

__global__ void k_fc2(const float* __restrict__ w, const float* __restrict__ bb)
{
    int o = blockIdx.x*8 + (threadIdx.x >> 5);
    int lane = threadIdx.x & 31;
    const float* wr = w + (size_t)o*512;
    float s = 0.f;
    for (int k=lane; k<512; k+=32) s += g_FC[k]*wr[k];
    for (int d=16; d; d>>=1) s += __shfl_down_sync(0xffffffffu, s, d);
    if (!lane) g_FC2[o] = sigm(s + bb[o]);
}

__global__ void k_out(const float* __restrict__ w, const float* __restrict__ bb,
                      float* __restrict__ out)
{
    __shared__ float logit[5];
    int wid = threadIdx.x >> 5, lane = threadIdx.x & 31;
    if (wid < 5) {
        float s = 0.f;
        for (int k=lane; k<256; k+=32) s += g_FC2[k]*w[wid*256 + k];
        for (int d=16; d; d>>=1) s += __shfl_down_sync(0xffffffffu, s, d);
        if (!lane) logit[wid] = s + bb[wid];
    }
    __syncthreads();
    if (threadIdx.x == 0) {
        float mx = logit[0];
        for (int c=1;c<5;c++) mx = fmaxf(mx, logit[c]);
        float sum = 0.f;
        for (int c=0;c<5;c++) sum += expf(logit[c]-mx);
        float l = logf(sum);
        for (int c=0;c<5;c++) out[c] = logit[c] - mx - l;
    }
}

// ---------------- host-side fixed tree schedule (N=512 heap, DFS post-order) ----------------
struct HostSched {
    int order[512]; int rankOf[512]; int height[512];
    int lvlCnt[10]; int lvlNodes[10][128];
    int leaf[256]; int nleaf;
};

static HostSched build_sched()
{
    HostSched s = {};
    int stN[64], stP[64]; int sp = 0, cnt = 0;
    stN[0] = 0; stP[0] = 0; sp = 1;
    while (sp) {
        int j = stN[sp-1], p = stP[sp-1];
        if (p < 2) {
            stP[sp-1] = p + 1;
            int c = 2*j + 1 + p;
            if (c < 512) { stN[sp] = c; stP[sp] = 0; sp++; }
        } else {
            s.order[cnt] = j; s.rankOf[j] = cnt; cnt++; sp--;
        }
    }
    for (int r = 0; r < 512; r++) {
        int j = s.order[r]; int h = 0;
        for (int k = 0; k < 2; k++) {
            int c = 2*j + 1 + k;
            if (c < 512) {
                int hh = s.height[s.rankOf[c]] + 1;
                if (hh > h) h = hh;
            }
        }
        s.height[r] = h;
        if (h == 0) s.leaf[s.nleaf++] = r;
        else        s.lvlNodes[h][s.lvlCnt[h]++] = r;
    }
    return s;
}

static const HostSched& sched() { static HostSched s = build_sched(); return s; }

// ---------------- launch ----------------
extern "C" void kernel_launch(void* const* d_in, const int* in_sizes, int n_in,
                              void* d_out, int out_size)
{
    const int*   linputs    = (const int*)  d_in[0];
    const int*   rinputs    = (const int*)  d_in[1];
    const int*   child_idx  = (const int*)  d_in[2];
    const float* child_mask = (const float*)d_in[3];
    const float* emb        = (const float*)d_in[4];
    const float* w_ioux     = (const float*)d_in[5];
    const float* b_ioux     = (const float*)d_in[6];
    const float* w_iouh     = (const float*)d_in[7];
    const float* b_iouh     = (const float*)d_in[8];
    const float* w_fx       = (const float*)d_in[9];
    const float* b_fx       = (const float*)d_in[10];
    const float* w_fh       = (const float*)d_in[11];
    const float* b_fh       = (const float*)d_in[12];
    const float* ws1        = (const float*)d_in[13];
    const float* ws2        = (const float*)d_in[14];
    const float* wf         = (const float*)d_in[15];
    const float* w_lat      = (const float*)d_in[16];
    const float* b_lat      = (const float*)d_in[17];
    const float* w_fc       = (const float*)d_in[18];
    const float* b_fc       = (const float*)d_in[19];
    const float* w_out      = (const float*)d_in[20];
    const float* b_out      = (const float*)d_in[21];
    const float* w_out1     = (const float*)d_in[22];
    const float* b_out1     = (const float*)d_in[23];
    float* out = (float*)d_out;

    float *pX, *pXIOU, *pXF, *pH, *pIOU, *pFP, *pHB, *pLOG, *pALPHA, *pM, *pLS;
    cudaGetSymbolAddress((void**)&pX,     g_X);
    cudaGetSymbolAddress((void**)&pXIOU,  g_XIOU);
    cudaGetSymbolAddress((void**)&pXF,    g_XF);
    cudaGetSymbolAddress((void**)&pH,     g_H);
    cudaGetSymbolAddress((void**)&pIOU,   g_IOU);
    cudaGetSymbolAddress((void**)&pFP,    g_FP);
    cudaGetSymbolAddress((void**)&pHB,    g_HB);
    cudaGetSymbolAddress((void**)&pLOG,   g_LOG);
    cudaGetSymbolAddress((void**)&pALPHA, g_ALPHA);
    cudaGetSymbolAddress((void**)&pM,     g_Mm);
    cudaGetSymbolAddress((void**)&pLS,    g_LS);

    const HostSched& S = sched();
    LvlArg dummy = {};

    // 1) embedding gather for both trees
    k_embed<<<1024, 256>>>(linputs, rinputs, emb);

    // 2) input projections (both trees stacked: M=1024)
    gemm64<0,true,0><<<dim3(48,16),256>>>(pX, w_ioux, b_ioux, pXIOU,
                                          1024, 3072, 1024, nullptr, nullptr, dummy, 1);
    gemm64<0,true,0><<<dim3(16,16),256>>>(pX, w_fx, b_fx, pXF,
                                          1024, 1024, 1024, nullptr, nullptr, dummy, 1);

    // 3) leaves
    {
        LeafArg lf = {};
        for (int i = 0; i < S.nleaf; i++) lf.r[i] = S.leaf[i];
        k_leaf<<<2048, 256>>>(lf, b_iouh);
    }

    // 4) internal levels by height
    for (int h = 1; h <= 9; h++) {
        int B = S.lvlCnt[h];
        if (B == 0) continue;
        LvlArg la = {};
        for (int i = 0; i < B; i++) la.r[i] = S.lvlNodes[h][i];
        dim3 g1(48, (2*B + 63)/64);
        gemm64<1,true,0><<<g1,256>>>(pH, w_iouh, nullptr, pIOU,
                                     2*B, 3072, 1024, child_idx, child_mask, la, B);
        dim3 g2(16, (4*B + 63)/64);
        gemm64<2,true,0><<<g2,256>>>(pH, w_fh, nullptr, pFP,
                                     4*B, 1024, 1024, child_idx, child_mask, la, B);
        int tot = 2*B*1024;
        k_point<<<(tot + 255)/256, 256>>>(child_idx, child_mask, la, B, b_iouh, b_fh);
    }

    // 5) attention
    gemm64<0,true,1><<<dim3(4,16),256>>>(pH, ws1, nullptr, pHB,
                                         1024, 256, 1024, nullptr, nullptr, dummy, 1);
    gemm64<0,true,0><<<dim3(1,16),256>>>(pHB, ws2, nullptr, pLOG,
                                         1024, 16, 256, nullptr, nullptr, dummy, 1);
    k_soft<<<32, 512>>>(out);
    for (int t = 0; t < 2; t++) {
        gemm64<0,false,0><<<dim3(16,1),256>>>(pALPHA + t*16*512, pH + (size_t)t*512*1024,
                                              nullptr, pM + t*16*1024,
                                              16, 1024, 512, nullptr, nullptr, dummy, 1);
    }

    // 6) head
    gemm64<0,false,2><<<dim3(16,1),256>>>(pM, wf, nullptr, pLS,
                                          32, 1024, 1024, nullptr, nullptr, dummy, 1);
    k_lat<<<4, 256>>>(w_lat, b_lat);
    k_fc<<<64, 256>>>(w_fc, b_fc);
    k_fc2<<<32, 256>>>(w_out, b_out);
    k_out<<<1, 160>>>(w_out1, b_out1, out);
}

// round 2
// speedup vs baseline: 1.0855x; 1.0855x over previous
#include <cuda_runtime.h>
#include <math.h>
#include <stdint.h>

// ---------------- static device scratch (no runtime allocation) ----------------
__device__ __align__(16) float g_X[2*512*1024];      // embedded inputs, both trees
__device__ __align__(16) float g_XIOU[2*512*3072];   // x @ w_ioux^T + b_ioux
__device__ __align__(16) float g_XF[2*512*1024];     // x @ w_fx^T + b_fx
__device__ __align__(16) float g_H[2*512*1024];      // hidden states by rank
__device__ __align__(16) float g_C[2*512*1024];      // cell states by rank
__device__ __align__(16) float g_IOU[256*3072];      // per-level hsum @ w_iouh^T
__device__ __align__(16) float g_FP[512*1024];       // per-level ch @ w_fh^T
__device__ __align__(16) float g_HB[1024*256];       // tanh(H @ ws1^T)
__device__ __align__(16) float g_LOG[1024*16];       // hbar @ ws2^T
__device__ __align__(16) float g_ALPHA[2*16*512];    // softmax attention
__device__ __align__(16) float g_Mm[32*1024];        // alphas @ H
__device__ __align__(16) float g_LS[32*1024];        // relu(M @ wf)
__device__ __align__(16) float g_FR[3072];
__device__ __align__(16) float g_FC[512];
__device__ __align__(16) float g_FC2[256];

struct LvlArg  { int r[128]; };
struct LeafArg { int r[256]; };

__device__ __forceinline__ float sigm(float x){ return 1.f/(1.f+expf(-x)); }

__device__ __forceinline__ uint32_t f2tf32(float x){
    uint32_t r;
    asm("cvt.rna.tf32.f32 %0, %1;" : "=r"(r) : "f"(x));
    return r;
}

__device__ __forceinline__ void mma_tf32(float c[4],
    uint32_t a0, uint32_t a1, uint32_t a2, uint32_t a3,
    uint32_t b0, uint32_t b1)
{
    asm volatile(
        "mma.sync.aligned.m16n8k8.row.col.f32.tf32.tf32.f32 "
        "{%0,%1,%2,%3}, {%4,%5,%6,%7}, {%8,%9}, {%0,%1,%2,%3};"
        : "+f"(c[0]), "+f"(c[1]), "+f"(c[2]), "+f"(c[3])
        : "r"(a0), "r"(a1), "r"(a2), "r"(a3), "r"(b0), "r"(b1));
}

// ---------------- tf32 tensor-core GEMM: C[M,N] = act(A @ op(B) + bias) ----------------
// AMODE 0: plain A (lda=K)
// AMODE 1: A row i -> masked sum of two child H rows (i = t*Bn + j), A = g_H base
// AMODE 2: A row i -> single masked child H row (i = t*2Bn + 2j + ck), A = g_H base
// BT true: B is [N,K] row-major (C = A@B^T); false: B is [K,N] row-major (C = A@B)
// ACT 0 none, 1 tanh, 2 relu
// Block: 64x64x16, 128 threads (4 warps), warp tile 32x32 via 8x m16n8k8.
template<int AMODE, bool BT, int ACT>
__global__ void gemm_tc(const float* __restrict__ A, const float* __restrict__ B,
                        const float* __restrict__ bias, float* __restrict__ C,
                        int M, int N, int K,
                        const int* __restrict__ cidx, const float* __restrict__ cmask,
                        LvlArg lvl, int Bn)
{
    __shared__ uint32_t As[64][20];   // [m][k], tf32 bits, pad 20 (80B rows, 16B aligned)
    __shared__ uint32_t Bs[64][20];   // [n][k], tf32 bits

    const int tid  = threadIdx.x;
    const int lane = tid & 31;
    const int warp = tid >> 5;
    const int wr   = warp >> 1;       // 0..1 : warp row (32 rows each)
    const int wc   = warp & 1;        // 0..1 : warp col (32 cols each)
    const int g    = lane >> 2;       // groupID 0..7
    const int tg   = lane & 3;        // thread-in-group 0..3

    const int rowBase = blockIdx.y * 64;
    const int colBase = blockIdx.x * 64;

    float acc[2][4][4];
    #pragma unroll
    for (int i=0;i<2;i++)
        #pragma unroll
        for (int j=0;j<4;j++)
            #pragma unroll
            for (int e=0;e<4;e++) acc[i][j][e] = 0.f;

    for (int k0 = 0; k0 < K; k0 += 16) {
        // ---- A tile: 64 rows x 16 k, 256 float4 loads over 128 threads ----
        #pragma unroll
        for (int it = 0; it < 2; it++) {
            int idx = tid + it*128;
            int row = idx >> 2;
            int k4  = (idx & 3) * 4;
            float4 av = make_float4(0.f,0.f,0.f,0.f);
            int gr = rowBase + row;
            if (gr < M) {
                if (AMODE == 0) {
                    av = *(const float4*)(A + (size_t)gr*K + k0 + k4);
                } else if (AMODE == 1) {
                    int t = gr / Bn, j = gr - t*Bn;
                    int r = lvl.r[j];
                    int c0 = cidx[2*r], c1 = cidx[2*r+1];
                    float m0 = cmask[2*r], m1 = cmask[2*r+1];
                    float4 h0 = *(const float4*)(A + ((size_t)(t*512 + c0))*1024 + k0 + k4);
                    float4 h1 = *(const float4*)(A + ((size_t)(t*512 + c1))*1024 + k0 + k4);
                    av.x = h0.x*m0 + h1.x*m1;
                    av.y = h0.y*m0 + h1.y*m1;
                    av.z = h0.z*m0 + h1.z*m1;
                    av.w = h0.w*m0 + h1.w*m1;
                } else {
                    int t = gr / (2*Bn), rem = gr - t*2*Bn, j = rem >> 1, ck = rem & 1;
                    int r = lvl.r[j];
                    int c = cidx[2*r+ck]; float mk = cmask[2*r+ck];
                    float4 h = *(const float4*)(A + ((size_t)(t*512 + c))*1024 + k0 + k4);
                    av.x = h.x*mk; av.y = h.y*mk; av.z = h.z*mk; av.w = h.w*mk;
                }
            }
            uint4 tv;
            tv.x = f2tf32(av.x); tv.y = f2tf32(av.y);
            tv.z = f2tf32(av.z); tv.w = f2tf32(av.w);
            *(uint4*)&As[row][k4] = tv;
        }

        // ---- B tile ----
        if (BT) {
            #pragma unroll
            for (int it = 0; it < 2; it++) {
                int idx = tid + it*128;
                int row = idx >> 2;          // n index
                int k4  = (idx & 3) * 4;
                float4 bv = make_float4(0.f,0.f,0.f,0.f);
                int gn = colBase + row;
                if (gn < N) bv = *(const float4*)(B + (size_t)gn*K + k0 + k4);
                uint4 tv;
                tv.x = f2tf32(bv.x); tv.y = f2tf32(bv.y);
                tv.z = f2tf32(bv.z); tv.w = f2tf32(bv.w);
                *(uint4*)&Bs[row][k4] = tv;
            }
        } else {
            #pragma unroll
            for (int it = 0; it < 2; it++) {
                int idx = tid + it*128;
                int k  = idx >> 4;           // 0..15
                int n4 = (idx & 15) * 4;
                float4 bv = *(const float4*)(B + (size_t)(k0+k)*N + colBase + n4);
                Bs[n4+0][k] = f2tf32(bv.x);
                Bs[n4+1][k] = f2tf32(bv.y);
                Bs[n4+2][k] = f2tf32(bv.z);
                Bs[n4+3][k] = f2tf32(bv.w);
            }
        }
        __syncthreads();

        // ---- compute: 2 k-steps of 8 ----
        #pragma unroll
        for (int ks = 0; ks < 16; ks += 8) {
            uint32_t a[2][4];
            #pragma unroll
            for (int i = 0; i < 2; i++) {
                int mb = wr*32 + i*16 + g;
                a[i][0] = As[mb    ][ks + tg];
                a[i][1] = As[mb + 8][ks + tg];
                a[i][2] = As[mb    ][ks + 4 + tg];
                a[i][3] = As[mb + 8][ks + 4 + tg];
            }
            uint32_t b[4][2];
            #pragma unroll
            for (int j = 0; j < 4; j++) {
                int nb = wc*32 + j*8 + g;
                b[j][0] = Bs[nb][ks + tg];
                b[j][1] = Bs[nb][ks + 4 + tg];
            }
            #pragma unroll
            for (int i = 0; i < 2; i++)
                #pragma unroll
                for (int j = 0; j < 4; j++)
                    mma_tf32(acc[i][j], a[i][0], a[i][1], a[i][2], a[i][3],
                             b[j][0], b[j][1]);
        }
        __syncthreads();
    }

    // ---- epilogue ----
    #pragma unroll
    for (int i = 0; i < 2; i++) {
        #pragma unroll
        for (int j = 0; j < 4; j++) {
            int r0 = rowBase + wr*32 + i*16 + g;
            int c0 = colBase + wc*32 + j*8 + tg*2;
            #pragma unroll
            for (int e = 0; e < 4; e++) {
                int row = r0 + ((e >> 1) ? 8 : 0);
                int col = c0 + (e & 1);
                if (row < M && col < N) {
                    float v = acc[i][j][e];
                    if (bias) v += bias[col];
                    if (ACT == 1) v = tanhf(v);
                    else if (ACT == 2) v = fmaxf(v, 0.f);
                    C[(size_t)row*N + col] = v;
                }
            }
        }
    }
}

// ---------------- pointwise kernels ----------------
__global__ void k_embed(const int* __restrict__ lin, const int* __restrict__ rin,
                        const float* __restrict__ emb)
{
    int row = blockIdx.x;               // 0..1023
    int t = row >> 9, n = row & 511;
    int tok = t ? rin[n] : lin[n];
    const float4* src = (const float4*)(emb + (size_t)tok*1024);
    float4* dst = (float4*)(g_X + (size_t)row*1024);
    dst[threadIdx.x] = src[threadIdx.x];
}

__global__ void k_leaf(LeafArg lf, const float* __restrict__ b_iouh)
{
    int gid = blockIdx.x*256 + threadIdx.x;   // 2*256*1024 total
    int i = gid >> 10, m = gid & 1023;
    int t = i >> 8, j = i & 255;
    int r = lf.r[j];
    size_t x = (size_t)(t*512 + r);
    float ig = g_XIOU[x*3072 + m]        + b_iouh[m];
    float og = g_XIOU[x*3072 + 1024 + m] + b_iouh[1024 + m];
    float ug = g_XIOU[x*3072 + 2048 + m] + b_iouh[2048 + m];
    float c = sigm(ig) * tanhf(ug);
    g_C[x*1024 + m] = c;
    g_H[x*1024 + m] = sigm(og) * tanhf(c);
}

__global__ void k_point(const int* __restrict__ cidx, const float* __restrict__ cmask,
                        LvlArg lvl, int Bn,
                        const float* __restrict__ b_iouh, const float* __restrict__ b_fh)
{
    int gid = blockIdx.x*256 + threadIdx.x;
    if (gid >= 2*Bn*1024) return;
    int i = gid >> 10, m = gid & 1023;
    int t = i / Bn, j = i - t*Bn;
    int r = lvl.r[j];
    size_t x = (size_t)(t*512 + r);
    float ig = g_XIOU[x*3072 + m]        + g_IOU[(size_t)i*3072 + m]        + b_iouh[m];
    float og = g_XIOU[x*3072 + 1024 + m] + g_IOU[(size_t)i*3072 + 1024 + m] + b_iouh[1024 + m];
    float ug = g_XIOU[x*3072 + 2048 + m] + g_IOU[(size_t)i*3072 + 2048 + m] + b_iouh[2048 + m];
    float xf = g_XF[x*1024 + m];
    float f0 = sigm(g_FP[(size_t)(2*i  )*1024 + m] + b_fh[m] + xf);
    float f1 = sigm(g_FP[(size_t)(2*i+1)*1024 + m] + b_fh[m] + xf);
    int c0 = cidx[2*r], c1 = cidx[2*r+1];
    float m0 = cmask[2*r], m1 = cmask[2*r+1];
    float cc0 = g_C[((size_t)(t*512 + c0))*1024 + m] * m0;
    float cc1 = g_C[((size_t)(t*512 + c1))*1024 + m] * m1;
    float c = sigm(ig)*tanhf(ug) + f0*cc0 + f1*cc1;
    g_C[x*1024 + m] = c;
    g_H[x*1024 + m] = sigm(og)*tanhf(c);
}

__global__ void k_soft(float* __restrict__ out)
{
    __shared__ float sh[512];
    int b = blockIdx.x;                 // t*16 + hop
    int t = b >> 4, hop = b & 15;
    int n = threadIdx.x;                // 512 threads
    float v = g_LOG[(size_t)(t*512 + n)*16 + hop];
    sh[n] = v; __syncthreads();
    for (int s=256; s>0; s>>=1){ if (n < s) sh[n] = fmaxf(sh[n], sh[n+s]); __syncthreads(); }
    float mx = sh[0]; __syncthreads();
    float e = expf(v - mx);
    sh[n] = e; __syncthreads();
    for (int s=256; s>0; s>>=1){ if (n < s) sh[n] += sh[n+s]; __syncthreads(); }
    float a = e / sh[0];
    g_ALPHA[(size_t)b*512 + n] = a;
    out[5 + t*8192 + hop*512 + n] = a;
}

__global__ void k_lat(const float* __restrict__ w_lat, const float* __restrict__ b_lat)
{
    int m = blockIdx.x*256 + threadIdx.x;   // 1024
    float lv = b_lat[0], rv = b_lat[0];
    #pragma unroll
    for (int h=0; h<16; h++) {
        float w = w_lat[h];
        lv += w * g_LS[h*1024 + m];
        rv += w * g_LS[(16 + h)*1024 + m];
    }
    g_FR[m]        = fabsf(lv - rv);
    g_FR[1024 + m] = lv * rv;
    g_FR[2048 + m] = 0.5f * (lv + rv);
}

__global__ void k_fc(const float* __restrict__ w, const float* __restrict__ bb)
{
    int o = blockIdx.x*8 + (threadIdx.x >> 5);
    int lane = threadIdx.x & 31;
    const float* wr = w + (size_t)o*3072;
    float s = 0.f;
    for (int k=lane; k<3072; k+=32) s += g_FR[k]*wr[k];
    for (int d=16; d; d>>=1) s += __shfl_down_sync(0xffffffffu, s, d);
    if (!lane) { float v = s + bb[o]; g_FC[o] = v > 0.f ? v : 0.01f*v; }
}

__global__ void k_fc2(const float* __restrict__ w, const float* __restrict__ bb)
{
    int o = blockIdx.x*8 + (threadIdx.x >> 5);
    int lane = threadIdx.x & 31;
    const float* wr = w + (size_t)o*512;
    float s = 0.f;
    for (int k=lane; k<512; k+=32) s += g_FC[k]*wr[k];
    for (int d=16; d; d>>=1) s += __shfl_down_sync(0xffffffffu, s, d);
    if (!lane) g_FC2[o] = sigm(s + bb[o]);
}

__global__ void k_out(const float* __restrict__ w, const float* __restrict__ bb,
                      float* __restrict__ out)
{
    __shared__ float logit[5];
    int wid = threadIdx.x >> 5, lane = threadIdx.x & 31;
    if (wid < 5) {
        float s = 0.f;
        for (int k=lane; k<256; k+=32) s += g_FC2[k]*w[wid*256 + k];
        for (int d=16; d; d>>=1) s += __shfl_down_sync(0xffffffffu, s, d);
        if (!lane) logit[wid] = s + bb[wid];
    }
    __syncthreads();
    if (threadIdx.x == 0) {
        float mx = logit[0];
        for (int c=1;c<5;c++) mx = fmaxf(mx, logit[c]);
        float sum = 0.f;
        for (int c=0;c<5;c++) sum += expf(logit[c]-mx);
        float l = logf(sum);
        for (int c=0;c<5;c++) out[c] = logit[c] - mx - l;
    }
}

// ---------------- host-side fixed tree schedule (N=512 heap, DFS post-order) ----------------
struct HostSched {
    int order[512]; int rankOf[512]; int height[512];
    int lvlCnt[10]; int lvlNodes[10][128];
    int leaf[256]; int nleaf;
};

static HostSched build_sched()
{
    HostSched s = {};
    int stN[64], stP[64]; int sp = 0, cnt = 0;
    stN[0] = 0; stP[0] = 0; sp = 1;
    while (sp) {
        int j = stN[sp-1], p = stP[sp-1];
        if (p < 2) {
            stP[sp-1] = p + 1;
            int c = 2*j + 1 + p;
            if (c < 512) { stN[sp] = c; stP[sp] = 0; sp++; }
        } else {
            s.order[cnt] = j; s.rankOf[j] = cnt; cnt++; sp--;
        }
    }
    for (int r = 0; r < 512; r++) {
        int j = s.order[r]; int h = 0;
        for (int k = 0; k < 2; k++) {
            int c = 2*j + 1 + k;
            if (c < 512) {
                int hh = s.height[s.rankOf[c]] + 1;
                if (hh > h) h = hh;
            }
        }
        s.height[r] = h;
        if (h == 0) s.leaf[s.nleaf++] = r;
        else        s.lvlNodes[h][s.lvlCnt[h]++] = r;
    }
    return s;
}

static const HostSched& sched() { static HostSched s = build_sched(); return s; }

// ---------------- launch ----------------
extern "C" void kernel_launch(void* const* d_in, const int* in_sizes, int n_in,
                              void* d_out, int out_size)
{
    const int*   linputs    = (const int*)  d_in[0];
    const int*   rinputs    = (const int*)  d_in[1];
    const int*   child_idx  = (const int*)  d_in[2];
    const float* child_mask = (const float*)d_in[3];
    const float* emb        = (const float*)d_in[4];
    const float* w_ioux     = (const float*)d_in[5];
    const float* b_ioux     = (const float*)d_in[6];
    const float* w_iouh     = (const float*)d_in[7];
    const float* b_iouh     = (const float*)d_in[8];
    const float* w_fx       = (const float*)d_in[9];
    const float* b_fx       = (const float*)d_in[10];
    const float* w_fh       = (const float*)d_in[11];
    const float* b_fh       = (const float*)d_in[12];
    const float* ws1        = (const float*)d_in[13];
    const float* ws2        = (const float*)d_in[14];
    const float* wf         = (const float*)d_in[15];
    const float* w_lat      = (const float*)d_in[16];
    const float* b_lat      = (const float*)d_in[17];
    const float* w_fc       = (const float*)d_in[18];
    const float* b_fc       = (const float*)d_in[19];
    const float* w_out      = (const float*)d_in[20];
    const float* b_out      = (const float*)d_in[21];
    const float* w_out1     = (const float*)d_in[22];
    const float* b_out1     = (const float*)d_in[23];
    float* out = (float*)d_out;

    float *pX, *pXIOU, *pXF, *pH, *pIOU, *pFP, *pHB, *pLOG, *pALPHA, *pM, *pLS;
    cudaGetSymbolAddress((void**)&pX,     g_X);
    cudaGetSymbolAddress((void**)&pXIOU,  g_XIOU);
    cudaGetSymbolAddress((void**)&pXF,    g_XF);
    cudaGetSymbolAddress((void**)&pH,     g_H);
    cudaGetSymbolAddress((void**)&pIOU,   g_IOU);
    cudaGetSymbolAddress((void**)&pFP,    g_FP);
    cudaGetSymbolAddress((void**)&pHB,    g_HB);
    cudaGetSymbolAddress((void**)&pLOG,   g_LOG);
    cudaGetSymbolAddress((void**)&pALPHA, g_ALPHA);
    cudaGetSymbolAddress((void**)&pM,     g_Mm);
    cudaGetSymbolAddress((void**)&pLS,    g_LS);

    const HostSched& S = sched();
    LvlArg dummy = {};

    // 1) embedding gather for both trees
    k_embed<<<1024, 256>>>(linputs, rinputs, emb);

    // 2) input projections (both trees stacked: M=1024)
    gemm_tc<0,true,0><<<dim3(48,16),128>>>(pX, w_ioux, b_ioux, pXIOU,
                                           1024, 3072, 1024, nullptr, nullptr, dummy, 1);
    gemm_tc<0,true,0><<<dim3(16,16),128>>>(pX, w_fx, b_fx, pXF,
                                           1024, 1024, 1024, nullptr, nullptr, dummy, 1);

    // 3) leaves
    {
        LeafArg lf = {};
        for (int i = 0; i < S.nleaf; i++) lf.r[i] = S.leaf[i];
        k_leaf<<<2048, 256>>>(lf, b_iouh);
    }

    // 4) internal levels by height
    for (int h = 1; h <= 9; h++) {
        int B = S.lvlCnt[h];
        if (B == 0) continue;
        LvlArg la = {};
        for (int i = 0; i < B; i++) la.r[i] = S.lvlNodes[h][i];
        dim3 g1(48, (2*B + 63)/64);
        gemm_tc<1,true,0><<<g1,128>>>(pH, w_iouh, nullptr, pIOU,
                                      2*B, 3072, 1024, child_idx, child_mask, la, B);
        dim3 g2(16, (4*B + 63)/64);
        gemm_tc<2,true,0><<<g2,128>>>(pH, w_fh, nullptr, pFP,
                                      4*B, 1024, 1024, child_idx, child_mask, la, B);
        int tot = 2*B*1024;
        k_point<<<(tot + 255)/256, 256>>>(child_idx, child_mask, la, B, b_iouh, b_fh);
    }

    // 5) attention
    gemm_tc<0,true,1><<<dim3(4,16),128>>>(pH, ws1, nullptr, pHB,
                                          1024, 256, 1024, nullptr, nullptr, dummy, 1);
    gemm_tc<0,true,0><<<dim3(1,16),128>>>(pHB, ws2, nullptr, pLOG,
                                          1024, 16, 256, nullptr, nullptr, dummy, 1);
    k_soft<<<32, 512>>>(out);
    for (int t = 0; t < 2; t++) {
        gemm_tc<0,false,0><<<dim3(16,1),128>>>(pALPHA + t*16*512, pH + (size_t)t*512*1024,
                                               nullptr, pM + t*16*1024,
                                               16, 1024, 512, nullptr, nullptr, dummy, 1);
    }

    // 6) head
    gemm_tc<0,false,2><<<dim3(16,1),128>>>(pM, wf, nullptr, pLS,
                                           32, 1024, 1024, nullptr, nullptr, dummy, 1);
    k_lat<<<4, 256>>>(w_lat, b_lat);
    k_fc<<<64, 256>>>(w_fc, b_fc);
    k_fc2<<<32, 256>>>(w_out, b_out);
    k_out<<<1, 160>>>(w_out1, b_out1, out);
}

// round 3
// speedup vs baseline: 2.1455x; 1.9765x over previous
#include <cuda_runtime.h>
#include <math.h>
#include <stdint.h>

// ---------------- static device scratch ----------------
__device__ __align__(16) float g_X[2*512*1024];
__device__ __align__(16) float g_XALL[2*512*4096];   // [iou(3072) | f(1024)] per row
__device__ __align__(16) float g_H[2*512*1024];
__device__ __align__(16) float g_C[2*512*1024];
__device__ __align__(16) float g_IOU[256*3072];
__device__ __align__(16) float g_FP[512*1024];
__device__ __align__(16) float g_HB[1024*256];
__device__ __align__(16) float g_LOG[1024*16];
__device__ __align__(16) float g_ALPHA[2*16*512];
__device__ __align__(16) float g_Mm[32*1024];
__device__ __align__(16) float g_LS[32*1024];
__device__ __align__(16) float g_FR[3072];
__device__ __align__(16) float g_FC[512];

// ---------------- compile-time tree schedule (N=512 heap, DFS post-order) ----------------
struct Sched {
    int leaf[256];
    int cnt[16];
    int lvl[16][128];
};

constexpr Sched make_sched() {
    Sched s{};
    int order[512] = {}; int rankOf[512] = {}; int height[512] = {};
    int stN[64] = {}; int stP[64] = {};
    int sp = 1, cnt = 0;
    stN[0] = 0; stP[0] = 0;
    while (sp) {
        int j = stN[sp-1], p = stP[sp-1];
        if (p < 2) {
            stP[sp-1] = p + 1;
            int c = 2*j + 1 + p;
            if (c < 512) { stN[sp] = c; stP[sp] = 0; sp++; }
        } else { order[cnt] = j; rankOf[j] = cnt; cnt++; sp--; }
    }
    int nleaf = 0;
    for (int r = 0; r < 512; r++) {
        int j = order[r]; int h = 0;
        for (int k = 0; k < 2; k++) {
            int c = 2*j + 1 + k;
            if (c < 512) { int hh = height[rankOf[c]] + 1; if (hh > h) h = hh; }
        }
        height[r] = h;
        if (h == 0) s.leaf[nleaf++] = r;
        else        s.lvl[h][s.cnt[h]++] = r;
    }
    return s;
}

constexpr Sched SCHED = make_sched();
__device__ const Sched d_S = make_sched();

__device__ __forceinline__ float sigm(float x){ return 1.f/(1.f+expf(-x)); }

__device__ __forceinline__ uint32_t f2tf32(float x){
    uint32_t r;
    asm("cvt.rna.tf32.f32 %0, %1;" : "=r"(r) : "f"(x));
    return r;
}

__device__ __forceinline__ void mma_tf32(float c[4],
    uint32_t a0, uint32_t a1, uint32_t a2, uint32_t a3,
    uint32_t b0, uint32_t b1)
{
    asm volatile(
        "mma.sync.aligned.m16n8k8.row.col.f32.tf32.tf32.f32 "
        "{%0,%1,%2,%3}, {%4,%5,%6,%7}, {%8,%9}, {%0,%1,%2,%3};"
        : "+f"(c[0]), "+f"(c[1]), "+f"(c[2]), "+f"(c[3])
        : "r"(a0), "r"(a1), "r"(a2), "r"(a3), "r"(b0), "r"(b1));
}

__device__ __forceinline__ void sts_row(uint32_t S[][20], int row, int k4, float4 v){
    uint4 t;
    t.x = f2tf32(v.x); t.y = f2tf32(v.y);
    t.z = f2tf32(v.z); t.w = f2tf32(v.w);
    *(uint4*)&S[row][k4] = t;
}

__device__ __forceinline__ void mma_tile16(float acc[2][4][4],
        const uint32_t As[][20], const uint32_t Bs[][20],
        int wr, int wc, int g, int tg)
{
    #pragma unroll
    for (int ks = 0; ks < 16; ks += 8) {
        uint32_t a[2][4];
        #pragma unroll
        for (int i = 0; i < 2; i++) {
            int mb = wr*32 + i*16 + g;
            a[i][0] = As[mb    ][ks + tg];
            a[i][1] = As[mb + 8][ks + tg];
            a[i][2] = As[mb    ][ks + 4 + tg];
            a[i][3] = As[mb + 8][ks + 4 + tg];
        }
        uint32_t b[4][2];
        #pragma unroll
        for (int j = 0; j < 4; j++) {
            int nb = wc*32 + j*8 + g;
            b[j][0] = Bs[nb][ks + tg];
            b[j][1] = Bs[nb][ks + 4 + tg];
        }
        #pragma unroll
        for (int i = 0; i < 2; i++)
            #pragma unroll
            for (int j = 0; j < 4; j++)
                mma_tf32(acc[i][j], a[i][0], a[i][1], a[i][2], a[i][3],
                         b[j][0], b[j][1]);
    }
}

// ---------------- big input-projection GEMM: g_XALL = g_X @ [w_ioux|w_fx]^T + [b1|b2] ----------------
// M=1024, N=4096, K=1024. Double-buffered, pipelined.
__global__ __launch_bounds__(128) void gemm_x(
    const float* __restrict__ w1, const float* __restrict__ w2,
    const float* __restrict__ b1, const float* __restrict__ b2)
{
    __shared__ uint32_t As[2][64][20];
    __shared__ uint32_t Bs[2][64][20];
    const int tid  = threadIdx.x;
    const int lane = tid & 31, warp = tid >> 5;
    const int wr = warp >> 1, wc = warp & 1;
    const int g = lane >> 2, tg = lane & 3;
    const int rowBase = blockIdx.y*64, colBase = blockIdx.x*64;

    float4 rA[2], rB[2];
    auto loadA = [&](int k0){
        #pragma unroll
        for (int it = 0; it < 2; it++) {
            int idx = tid + it*128, row = idx >> 2, k4 = (idx & 3)*4;
            rA[it] = *(const float4*)(g_X + (size_t)(rowBase+row)*1024 + k0 + k4);
        }
    };
    auto loadB = [&](int k0){
        #pragma unroll
        for (int it = 0; it < 2; it++) {
            int idx = tid + it*128, row = idx >> 2, k4 = (idx & 3)*4;
            int gn = colBase + row;
            const float* src = (gn < 3072) ? (w1 + (size_t)gn*1024)
                                           : (w2 + (size_t)(gn-3072)*1024);
            rB[it] = *(const float4*)(src + k0 + k4);
        }
    };
    auto stsAll = [&](int buf){
        #pragma unroll
        for (int it = 0; it < 2; it++) {
            int idx = tid + it*128, row = idx >> 2, k4 = (idx & 3)*4;
            sts_row(As[buf], row, k4, rA[it]);
            sts_row(Bs[buf], row, k4, rB[it]);
        }
    };

    float acc[2][4][4];
    #pragma unroll
    for (int i=0;i<2;i++) for (int j=0;j<4;j++) for (int e=0;e<4;e++) acc[i][j][e]=0.f;

    loadA(0); loadB(0); stsAll(0); __syncthreads();
    int buf = 0;
    for (int k0 = 16; ; k0 += 16) {
        bool more = (k0 < 1024);
        if (more) { loadA(k0); loadB(k0); }
        mma_tile16(acc, As[buf], Bs[buf], wr, wc, g, tg);
        if (!more) break;
        buf ^= 1;
        stsAll(buf);
        __syncthreads();
    }

    #pragma unroll
    for (int i = 0; i < 2; i++) {
        #pragma unroll
        for (int j = 0; j < 4; j++) {
            int r0 = rowBase + wr*32 + i*16 + g;
            int c0 = colBase + wc*32 + j*8 + tg*2;
            #pragma unroll
            for (int e = 0; e < 4; e++) {
                int row = r0 + ((e >> 1) ? 8 : 0);
                int col = c0 + (e & 1);
                float bias = (col < 3072) ? b1[col] : b2[col-3072];
                g_XALL[(size_t)row*4096 + col] = acc[i][j][e] + bias;
            }
        }
    }
}

// ---------------- per-level merged GEMM (z=0: iou hsum@w_iouh^T; z=1: child@w_fh^T) ----------------
__global__ __launch_bounds__(128) void gemm_lvl(
    const int* __restrict__ cidx, const float* __restrict__ cmask,
    const float* __restrict__ w_iouh, const float* __restrict__ w_fh,
    int h, int Bn)
{
    const int z = blockIdx.z;
    const int Mrows = z ? 4*Bn : 2*Bn;
    const int N = z ? 1024 : 3072;
    const int rowBase = blockIdx.y*64, colBase = blockIdx.x*64;
    if (rowBase >= Mrows || colBase >= N) return;
    const float* W = z ? w_fh : w_iouh;
    float* Cout = z ? g_FP : g_IOU;

    __shared__ uint32_t As[2][64][20];
    __shared__ uint32_t Bs[2][64][20];
    const int tid  = threadIdx.x;
    const int lane = tid & 31, warp = tid >> 5;
    const int wr = warp >> 1, wc = warp & 1;
    const int g = lane >> 2, tg = lane & 3;

    float4 rA[2], rB[2];
    auto loadA = [&](int k0){
        #pragma unroll
        for (int it = 0; it < 2; it++) {
            int idx = tid + it*128, row = idx >> 2, k4 = (idx & 3)*4;
            float4 v = make_float4(0.f,0.f,0.f,0.f);
            int gr = rowBase + row;
            if (gr < Mrows) {
                if (z == 0) {
                    int t = gr >= Bn; int j = gr - (t ? Bn : 0);
                    int r = d_S.lvl[h][j];
                    int c0 = cidx[2*r], c1 = cidx[2*r+1];
                    float m0 = cmask[2*r], m1 = cmask[2*r+1];
                    float4 h0 = *(const float4*)(g_H + ((size_t)(t*512+c0))*1024 + k0 + k4);
                    float4 h1 = *(const float4*)(g_H + ((size_t)(t*512+c1))*1024 + k0 + k4);
                    v.x = h0.x*m0 + h1.x*m1; v.y = h0.y*m0 + h1.y*m1;
                    v.z = h0.z*m0 + h1.z*m1; v.w = h0.w*m0 + h1.w*m1;
                } else {
                    int t = gr >= 2*Bn; int rem = gr - (t ? 2*Bn : 0);
                    int j = rem >> 1, ck = rem & 1;
                    int r = d_S.lvl[h][j];
                    int c = cidx[2*r+ck]; float mk = cmask[2*r+ck];
                    float4 hh = *(const float4*)(g_H + ((size_t)(t*512+c))*1024 + k0 + k4);
                    v.x = hh.x*mk; v.y = hh.y*mk; v.z = hh.z*mk; v.w = hh.w*mk;
                }
            }
            rA[it] = v;
        }
    };
    auto loadB = [&](int k0){
        #pragma unroll
        for (int it = 0; it < 2; it++) {
            int idx = tid + it*128, row = idx >> 2, k4 = (idx & 3)*4;
            rB[it] = *(const float4*)(W + (size_t)(colBase+row)*1024 + k0 + k4);
        }
    };
    auto stsAll = [&](int buf){
        #pragma unroll
        for (int it = 0; it < 2; it++) {
            int idx = tid + it*128, row = idx >> 2, k4 = (idx & 3)*4;
            sts_row(As[buf], row, k4, rA[it]);
            sts_row(Bs[buf], row, k4, rB[it]);
        }
    };

    float acc[2][4][4];
    #pragma unroll
    for (int i=0;i<2;i++) for (int j=0;j<4;j++) for (int e=0;e<4;e++) acc[i][j][e]=0.f;

    loadA(0); loadB(0); stsAll(0); __syncthreads();
    int buf = 0;
    for (int k0 = 16; ; k0 += 16) {
        bool more = (k0 < 1024);
        if (more) { loadA(k0); loadB(k0); }
        mma_tile16(acc, As[buf], Bs[buf], wr, wc, g, tg);
        if (!more) break;
        buf ^= 1;
        stsAll(buf);
        __syncthreads();
    }

    #pragma unroll
    for (int i = 0; i < 2; i++) {
        #pragma unroll
        for (int j = 0; j < 4; j++) {
            int r0 = rowBase + wr*32 + i*16 + g;
            int c0 = colBase + wc*32 + j*8 + tg*2;
            #pragma unroll
            for (int e = 0; e < 4; e++) {
                int row = r0 + ((e >> 1) ? 8 : 0);
                int col = c0 + (e & 1);
                if (row < Mrows)
                    Cout[(size_t)row*N + col] = acc[i][j][e];
            }
        }
    }
}

// ---------------- generic small GEMM (AMODE0), batched via gridDim.z ----------------
// BT true: C = A@B^T (B [N,K]); false: C = A@B (B [K,N], N multiple of 64)
// ACT 0 none, 1 tanh, 2 relu
template<bool BT, int ACT>
__global__ __launch_bounds__(128) void gemm_s(
    const float* __restrict__ A, const float* __restrict__ B,
    const float* __restrict__ bias, float* __restrict__ C,
    int M, int N, int K, int sA, int sB, int sC)
{
    A += (size_t)blockIdx.z * sA;
    B += (size_t)blockIdx.z * sB;
    C += (size_t)blockIdx.z * sC;

    __shared__ uint32_t As[2][64][20];
    __shared__ uint32_t Bs[2][64][20];
    const int tid  = threadIdx.x;
    const int lane = tid & 31, warp = tid >> 5;
    const int wr = warp >> 1, wc = warp & 1;
    const int g = lane >> 2, tg = lane & 3;
    const int rowBase = blockIdx.y*64, colBase = blockIdx.x*64;

    float4 rA[2], rB[2];
    auto loadA = [&](int k0){
        #pragma unroll
        for (int it = 0; it < 2; it++) {
            int idx = tid + it*128, row = idx >> 2, k4 = (idx & 3)*4;
            int gr = rowBase + row;
            rA[it] = (gr < M) ? *(const float4*)(A + (size_t)gr*K + k0 + k4)
                              : make_float4(0.f,0.f,0.f,0.f);
        }
    };
    auto loadB = [&](int k0){
        #pragma unroll
        for (int it = 0; it < 2; it++) {
            int idx = tid + it*128;
            if (BT) {
                int row = idx >> 2, k4 = (idx & 3)*4;
                int gn = colBase + row;
                rB[it] = (gn < N) ? *(const float4*)(B + (size_t)gn*K + k0 + k4)
                                  : make_float4(0.f,0.f,0.f,0.f);
            } else {
                int k = idx >> 4, n4 = (idx & 15)*4;
                rB[it] = *(const float4*)(B + (size_t)(k0+k)*N + colBase + n4);
            }
        }
    };
    auto stsAll = [&](int buf){
        #pragma unroll
        for (int it = 0; it < 2; it++) {
            int idx = tid + it*128;
            int rowA = idx >> 2, k4 = (idx & 3)*4;
            sts_row(As[buf], rowA, k4, rA[it]);
            if (BT) {
                sts_row(Bs[buf], rowA, k4, rB[it]);
            } else {
                int k = idx >> 4, n4 = (idx & 15)*4;
                Bs[buf][n4+0][k] = f2tf32(rB[it].x);
                Bs[buf][n4+1][k] = f2tf32(rB[it].y);
                Bs[buf][n4+2][k] = f2tf32(rB[it].z);
                Bs[buf][n4+3][k] = f2tf32(rB[it].w);
            }
        }
    };

    float acc[2][4][4];
    #pragma unroll
    for (int i=0;i<2;i++) for (int j=0;j<4;j++) for (int e=0;e<4;e++) acc[i][j][e]=0.f;

    loadA(0); loadB(0); stsAll(0); __syncthreads();
    int buf = 0;
    for (int k0 = 16; ; k0 += 16) {
        bool more = (k0 < K);
        if (more) { loadA(k0); loadB(k0); }
        mma_tile16(acc, As[buf], Bs[buf], wr, wc, g, tg);
        if (!more) break;
        buf ^= 1;
        stsAll(buf);
        __syncthreads();
    }

    #pragma unroll
    for (int i = 0; i < 2; i++) {
        #pragma unroll
        for (int j = 0; j < 4; j++) {
            int r0 = rowBase + wr*32 + i*16 + g;
            int c0 = colBase + wc*32 + j*8 + tg*2;
            #pragma unroll
            for (int e = 0; e < 4; e++) {
                int row = r0 + ((e >> 1) ? 8 : 0);
                int col = c0 + (e & 1);
                if (row < M && col < N) {
                    float v = acc[i][j][e];
                    if (bias) v += bias[col];
                    if (ACT == 1) v = tanhf(v);
                    else if (ACT == 2) v = fmaxf(v, 0.f);
                    C[(size_t)row*N + col] = v;
                }
            }
        }
    }
}

// ---------------- pointwise kernels ----------------
__global__ void k_embed(const int* __restrict__ lin, const int* __restrict__ rin,
                        const float* __restrict__ emb)
{
    int row = blockIdx.x;
    int t = row >> 9, n = row & 511;
    int tok = t ? rin[n] : lin[n];
    const float4* src = (const float4*)(emb + (size_t)tok*1024);
    float4* dst = (float4*)(g_X + (size_t)row*1024);
    dst[threadIdx.x] = src[threadIdx.x];
}

__global__ void k_leaf(const float* __restrict__ b_iouh)
{
    int gid = blockIdx.x*256 + threadIdx.x;   // 2*256*1024
    int i = gid >> 10, m = gid & 1023;
    int t = i >> 8, j = i & 255;
    int r = d_S.leaf[j];
    size_t x = (size_t)(t*512 + r);
    float ig = g_XALL[x*4096 + m]        + b_iouh[m];
    float og = g_XALL[x*4096 + 1024 + m] + b_iouh[1024 + m];
    float ug = g_XALL[x*4096 + 2048 + m] + b_iouh[2048 + m];
    float c = sigm(ig) * tanhf(ug);
    g_C[x*1024 + m] = c;
    g_H[x*1024 + m] = sigm(og) * tanhf(c);
}

__global__ void k_point(const int* __restrict__ cidx, const float* __restrict__ cmask,
                        int h, int Bn,
                        const float* __restrict__ b_iouh, const float* __restrict__ b_fh)
{
    int gid = blockIdx.x*256 + threadIdx.x;
    if (gid >= 2*Bn*1024) return;
    int i = gid >> 10, m = gid & 1023;
    int t = i >= Bn; int j = i - (t ? Bn : 0);
    int r = d_S.lvl[h][j];
    size_t x = (size_t)(t*512 + r);
    float ig = g_XALL[x*4096 + m]        + g_IOU[(size_t)i*3072 + m]        + b_iouh[m];
    float og = g_XALL[x*4096 + 1024 + m] + g_IOU[(size_t)i*3072 + 1024 + m] + b_iouh[1024 + m];
    float ug = g_XALL[x*4096 + 2048 + m] + g_IOU[(size_t)i*3072 + 2048 + m] + b_iouh[2048 + m];
    float xf = g_XALL[x*4096 + 3072 + m];
    float f0 = sigm(g_FP[(size_t)(2*i  )*1024 + m] + b_fh[m] + xf);
    float f1 = sigm(g_FP[(size_t)(2*i+1)*1024 + m] + b_fh[m] + xf);
    int c0 = cidx[2*r], c1 = cidx[2*r+1];
    float m0 = cmask[2*r], m1 = cmask[2*r+1];
    float cc0 = g_C[((size_t)(t*512 + c0))*1024 + m] * m0;
    float cc1 = g_C[((size_t)(t*512 + c1))*1024 + m] * m1;
    float c = sigm(ig)*tanhf(ug) + f0*cc0 + f1*cc1;
    g_C[x*1024 + m] = c;
    g_H[x*1024 + m] = sigm(og)*tanhf(c);
}

__global__ void k_soft(float* __restrict__ out)
{
    __shared__ float sh[512];
    int b = blockIdx.x;                 // t*16 + hop
    int t = b >> 4, hop = b & 15;
    int n = threadIdx.x;
    float v = g_LOG[(size_t)(t*512 + n)*16 + hop];
    sh[n] = v; __syncthreads();
    for (int s=256; s>0; s>>=1){ if (n < s) sh[n] = fmaxf(sh[n], sh[n+s]); __syncthreads(); }
    float mx = sh[0]; __syncthreads();
    float e = expf(v - mx);
    sh[n] = e; __syncthreads();
    for (int s=256; s>0; s>>=1){ if (n < s) sh[n] += sh[n+s]; __syncthreads(); }
    float a = e / sh[0];
    g_ALPHA[(size_t)b*512 + n] = a;
    out[5 + t*8192 + hop*512 + n] = a;
}

__global__ void k_lat(const float* __restrict__ w_lat, const float* __restrict__ b_lat)
{
    int m = blockIdx.x*256 + threadIdx.x;
    float lv = b_lat[0], rv = b_lat[0];
    #pragma unroll
    for (int h=0; h<16; h++) {
        float w = w_lat[h];
        lv += w * g_LS[h*1024 + m];
        rv += w * g_LS[(16 + h)*1024 + m];
    }
    g_FR[m]        = fabsf(lv - rv);
    g_FR[1024 + m] = lv * rv;
    g_FR[2048 + m] = 0.5f * (lv + rv);
}

__global__ void k_fc(const float* __restrict__ w, const float* __restrict__ bb)
{
    int o = blockIdx.x*8 + (threadIdx.x >> 5);
    int lane = threadIdx.x & 31;
    const float* wr = w + (size_t)o*3072;
    float s = 0.f;
    for (int k=lane; k<3072; k+=32) s += g_FR[k]*wr[k];
    for (int d=16; d; d>>=1) s += __shfl_down_sync(0xffffffffu, s, d);
    if (!lane) { float v = s + bb[o]; g_FC[o] = v > 0.f ? v : 0.01f*v; }
}

__global__ void k_fc2out(const float* __restrict__ w_out, const float* __restrict__ b_out,
                         const float* __restrict__ w_out1, const float* __restrict__ b_out1,
                         float* __restrict__ out)
{
    __shared__ float fc2[256];
    __shared__ float logit[5];
    int tid = threadIdx.x;             // 256
    int wid = tid >> 5, lane = tid & 31;
    // stage 1: fc2[o] = sigm(fc @ w_out[o] + b), 256 outputs, 8 warps x 32 each
    for (int it = 0; it < 4; it++) {
        int o = wid*32 + (it << 3) + (lane >> 2);   // 8 outputs per warp per it, 4 lanes each
        float s = 0.f;
        for (int k = (lane & 3); k < 512; k += 4) s += g_FC[k]*w_out[(size_t)o*512 + k];
        // reduce within 4-lane group
        s += __shfl_down_sync(0xffffffffu, s, 2);
        s += __shfl_down_sync(0xffffffffu, s, 1);
        if ((lane & 3) == 0) fc2[o] = sigm(s + b_out[o]);
    }
    __syncthreads();
    // stage 2: 5 logits
    if (wid < 5) {
        float s = 0.f;
        for (int k = lane; k < 256; k += 32) s += fc2[k]*w_out1[wid*256 + k];
        for (int d = 16; d; d >>= 1) s += __shfl_down_sync(0xffffffffu, s, d);
        if (!lane) logit[wid] = s + b_out1[wid];
    }
    __syncthreads();
    if (tid == 0) {
        float mx = logit[0];
        for (int c=1;c<5;c++) mx = fmaxf(mx, logit[c]);
        float sum = 0.f;
        for (int c=0;c<5;c++) sum += expf(logit[c]-mx);
        float l = logf(sum);
        for (int c=0;c<5;c++) out[c] = logit[c] - mx - l;
    }
}

// ---------------- launch ----------------
extern "C" void kernel_launch(void* const* d_in, const int* in_sizes, int n_in,
                              void* d_out, int out_size)
{
    const int*   linputs    = (const int*)  d_in[0];
    const int*   rinputs    = (const int*)  d_in[1];
    const int*   child_idx  = (const int*)  d_in[2];
    const float* child_mask = (const float*)d_in[3];
    const float* emb        = (const float*)d_in[4];
    const float* w_ioux     = (const float*)d_in[5];
    const float* b_ioux     = (const float*)d_in[6];
    const float* w_iouh     = (const float*)d_in[7];
    const float* b_iouh     = (const float*)d_in[8];
    const float* w_fx       = (const float*)d_in[9];
    const float* b_fx       = (const float*)d_in[10];
    const float* w_fh       = (const float*)d_in[11];
    const float* b_fh       = (const float*)d_in[12];
    const float* ws1        = (const float*)d_in[13];
    const float* ws2        = (const float*)d_in[14];
    const float* wf         = (const float*)d_in[15];
    const float* w_lat      = (const float*)d_in[16];
    const float* b_lat      = (const float*)d_in[17];
    const float* w_fc       = (const float*)d_in[18];
    const float* b_fc       = (const float*)d_in[19];
    const float* w_out      = (const float*)d_in[20];
    const float* b_out      = (const float*)d_in[21];
    const float* w_out1     = (const float*)d_in[22];
    const float* b_out1     = (const float*)d_in[23];
    float* out = (float*)d_out;

    float *pH, *pHB, *pLOG, *pALPHA, *pM, *pLS;
    cudaGetSymbolAddress((void**)&pH,     g_H);
    cudaGetSymbolAddress((void**)&pHB,    g_HB);
    cudaGetSymbolAddress((void**)&pLOG,   g_LOG);
    cudaGetSymbolAddress((void**)&pALPHA, g_ALPHA);
    cudaGetSymbolAddress((void**)&pM,     g_Mm);
    cudaGetSymbolAddress((void**)&pLS,    g_LS);

    // 1) embedding gather
    k_embed<<<1024, 256>>>(linputs, rinputs, emb);

    // 2) fused input projections: [iou | f], M=1024, N=4096, K=1024
    gemm_x<<<dim3(64,16), 128>>>(w_ioux, w_fx, b_ioux, b_fx);

    // 3) leaves
    k_leaf<<<2048, 256>>>(b_iouh);

    // 4) internal levels (fused iou+f GEMM per level, then pointwise)
    for (int h = 1; h <= 15; h++) {
        int B = SCHED.cnt[h];
        if (B == 0) continue;
        int gy = (4*B + 63)/64; if (gy < 1) gy = 1;
        gemm_lvl<<<dim3(48, gy, 2), 128>>>(child_idx, child_mask, w_iouh, w_fh, h, B);
        k_point<<<(2*B*1024 + 255)/256, 256>>>(child_idx, child_mask, h, B, b_iouh, b_fh);
    }

    // 5) attention
    gemm_s<true,1><<<dim3(4,16,1), 128>>>(pH, ws1, nullptr, pHB,
                                          1024, 256, 1024, 0, 0, 0);
    gemm_s<true,0><<<dim3(1,16,1), 128>>>(pHB, ws2, nullptr, pLOG,
                                          1024, 16, 256, 0, 0, 0);
    k_soft<<<32, 512>>>(out);
    gemm_s<false,0><<<dim3(16,1,2), 128>>>(pALPHA, pH, nullptr, pM,
                                           16, 1024, 512, 16*512, 512*1024, 16*1024);

    // 6) head
    gemm_s<false,2><<<dim3(16,1,1), 128>>>(pM, wf, nullptr, pLS,
                                           32, 1024, 1024, 0, 0, 0);
    k_lat<<<4, 256>>>(w_lat, b_lat);
    k_fc<<<64, 256>>>(w_fc, b_fc);
    k_fc2out<<<1, 256>>>(w_out, b_out, w_out1, b_out1, out);
}

// round 6
// speedup vs baseline: 2.8036x; 1.3067x over previous
#include <cuda_runtime.h>
#include <cuda_fp16.h>
#include <math.h>
#include <stdint.h>

// ---------------- static device scratch ----------------
__device__ __align__(16) float g_X[2*512*1024];
__device__ __align__(16) float g_XALL[2*512*4096];   // [iou(3072) | f(1024)] per row
__device__ __align__(16) float g_H[2*512*1024];
__device__ __align__(16) float g_C[2*512*1024];
__device__ __align__(16) float g_IOU[256*3072];
__device__ __align__(16) float g_FP[512*1024];
__device__ __align__(16) float g_HB[1024*256];
__device__ __align__(16) float g_LOG[1024*16];
__device__ __align__(16) float g_ALPHA[2*16*512];
__device__ __align__(16) float g_Mm[32*1024];
__device__ __align__(16) float g_LS[32*1024];
__device__ __align__(16) float g_FR[3072];
__device__ __align__(16) float g_FC[512];

// ---------------- compile-time tree schedule (N=512 heap, DFS post-order) ----------------
struct Sched {
    int leaf[256];
    int cnt[16];
    int lvl[16][128];
};

constexpr Sched make_sched() {
    Sched s{};
    int order[512] = {}; int rankOf[512] = {}; int height[512] = {};
    int stN[64] = {}; int stP[64] = {};
    int sp = 1, cnt = 0;
    stN[0] = 0; stP[0] = 0;
    while (sp) {
        int j = stN[sp-1], p = stP[sp-1];
        if (p < 2) {
            stP[sp-1] = p + 1;
            int c = 2*j + 1 + p;
            if (c < 512) { stN[sp] = c; stP[sp] = 0; sp++; }
        } else { order[cnt] = j; rankOf[j] = cnt; cnt++; sp--; }
    }
    int nleaf = 0;
    for (int r = 0; r < 512; r++) {
        int j = order[r]; int h = 0;
        for (int k = 0; k < 2; k++) {
            int c = 2*j + 1 + k;
            if (c < 512) { int hh = height[rankOf[c]] + 1; if (hh > h) h = hh; }
        }
        height[r] = h;
        if (h == 0) s.leaf[nleaf++] = r;
        else        s.lvl[h][s.cnt[h]++] = r;
    }
    return s;
}

constexpr Sched SCHED = make_sched();
__device__ const Sched d_S = make_sched();

__device__ __forceinline__ float sigm(float x){ return 1.f/(1.f+expf(-x)); }

// ---------------- fp16 MMA (m16n8k16, fp32 accum) ----------------
__device__ __forceinline__ void mma_f16(float c[4],
    uint32_t a0, uint32_t a1, uint32_t a2, uint32_t a3,
    uint32_t b0, uint32_t b1)
{
    asm volatile(
        "mma.sync.aligned.m16n8k16.row.col.f32.f16.f16.f32 "
        "{%0,%1,%2,%3}, {%4,%5,%6,%7}, {%8,%9}, {%0,%1,%2,%3};"
        : "+f"(c[0]), "+f"(c[1]), "+f"(c[2]), "+f"(c[3])
        : "r"(a0), "r"(a1), "r"(a2), "r"(a3), "r"(b0), "r"(b1));
}

__device__ __forceinline__ uint2 f4_to_h4(float4 v){
    __half2 p0 = __floats2half2_rn(v.x, v.y);
    __half2 p1 = __floats2half2_rn(v.z, v.w);
    uint2 r; r.x = *(uint32_t*)&p0; r.y = *(uint32_t*)&p1;
    return r;
}

// ---------------- fp16 tensor-core GEMM, 128x64 tile, k-chunk 32, 256 threads ------
// MODE 0: A = g_X (M=1024,K=1024), B rows split [w_ioux | w_fx] (N=4096), C = g_XALL + split bias
// MODE 1: per-level; z = blockIdx.z:
//         z=0: A row = masked child-H sum   (M=2Bn), B=w1=w_iouh (N=3072), C=g_IOU
//         z=1: A row = single masked child  (M=4Bn), B=w2=w_fh  (N=1024), C=g_FP
template<int MODE>
__global__ __launch_bounds__(256)
void gemm_h(const float* __restrict__ w1, const float* __restrict__ w2,
            const float* __restrict__ b1, const float* __restrict__ b2,
            const int* __restrict__ cidx, const float* __restrict__ cmask,
            int h, int Bn)
{
    int Mrows, Nn, z = 0;
    const float* Bw = w1;
    float* Cout = g_XALL;
    if (MODE == 0) {
        Mrows = 1024; Nn = 4096;
    } else {
        z = blockIdx.z;
        Mrows = z ? 4*Bn : 2*Bn;
        Nn    = z ? 1024 : 3072;
        Bw    = z ? w2 : w1;
        Cout  = z ? g_FP : g_IOU;
    }
    const int rowBase = blockIdx.y * 128;
    const int colBase = blockIdx.x * 64;
    if (rowBase >= Mrows || colBase >= Nn) return;

    // k-pair layout: row-major [r][16 pairs], stride 20 words (80B) for swizzle-free banks
    __shared__ uint32_t As[2][128][20];
    __shared__ uint32_t Bs[2][64][20];

    const int tid  = threadIdx.x;
    const int lane = tid & 31, warp = tid >> 5;
    const int wr = warp >> 1;            // 0..3  (32-row slice)
    const int wc = warp & 1;             // 0..1  (32-col slice)
    const int g  = lane >> 2, tg = lane & 3;

    float4 rA[4], rB[2];
    auto loadA = [&](int k0){
        #pragma unroll
        for (int it = 0; it < 4; it++) {
            int idx = tid + (it << 8);       // 0..1023
            int row = idx >> 3, q = idx & 7; // q: float4 within 32 floats
            int k4 = q << 2;
            float4 v = make_float4(0.f,0.f,0.f,0.f);
            int gr = rowBase + row;
            if (MODE == 0) {
                v = *(const float4*)(g_X + (size_t)gr*1024 + k0 + k4);
            } else if (gr < Mrows) {
                if (z == 0) {
                    int t = gr >= Bn; int j = gr - (t ? Bn : 0);
                    int r = d_S.lvl[h][j];
                    int c0 = cidx[2*r], c1 = cidx[2*r+1];
                    float m0 = cmask[2*r], m1 = cmask[2*r+1];
                    const float4 h0 = *(const float4*)(g_H + ((size_t)(t*512+c0))*1024 + k0 + k4);
                    const float4 h1 = *(const float4*)(g_H + ((size_t)(t*512+c1))*1024 + k0 + k4);
                    v.x = h0.x*m0 + h1.x*m1; v.y = h0.y*m0 + h1.y*m1;
                    v.z = h0.z*m0 + h1.z*m1; v.w = h0.w*m0 + h1.w*m1;
                } else {
                    int t = gr >= 2*Bn; int rem = gr - (t ? 2*Bn : 0);
                    int j = rem >> 1, ck = rem & 1;
                    int r = d_S.lvl[h][j];
                    int cc = cidx[2*r+ck]; float mk = cmask[2*r+ck];
                    const float4 hh = *(const float4*)(g_H + ((size_t)(t*512+cc))*1024 + k0 + k4);
                    v.x = hh.x*mk; v.y = hh.y*mk; v.z = hh.z*mk; v.w = hh.w*mk;
                }
            }
            rA[it] = v;
        }
    };
    auto loadB = [&](int k0){
        #pragma unroll
        for (int it = 0; it < 2; it++) {
            int idx = tid + (it << 8);       // 0..511
            int row = idx >> 3, q = idx & 7;
            int k4 = q << 2;
            int gn = colBase + row;
            const float* src;
            if (MODE == 0) src = (gn < 3072) ? (w1 + (size_t)gn*1024)
                                             : (w2 + (size_t)(gn-3072)*1024);
            else           src = Bw + (size_t)gn*1024;
            rB[it] = *(const float4*)(src + k0 + k4);
        }
    };
    auto stsAll = [&](int buf){
        #pragma unroll
        for (int it = 0; it < 4; it++) {
            int idx = tid + (it << 8);
            int row = idx >> 3, q = idx & 7;
            *(uint2*)&As[buf][row][q*2] = f4_to_h4(rA[it]);
        }
        #pragma unroll
        for (int it = 0; it < 2; it++) {
            int idx = tid + (it << 8);
            int row = idx >> 3, q = idx & 7;
            *(uint2*)&Bs[buf][row][q*2] = f4_to_h4(rB[it]);
        }
    };

    float acc[2][4][4];
    #pragma unroll
    for (int i=0;i<2;i++) for (int j=0;j<4;j++) for (int e=0;e<4;e++) acc[i][j][e]=0.f;

    loadA(0); loadB(0); stsAll(0); __syncthreads();
    int buf = 0;
    for (int k0 = 32; ; k0 += 32) {
        bool more = (k0 < 1024);
        if (more) { loadA(k0); loadB(k0); }
        // compute on buf: 2 k16-steps
        #pragma unroll
        for (int s = 0; s < 2; s++) {
            const int kp = s*8;
            uint32_t a[2][4];
            #pragma unroll
            for (int i = 0; i < 2; i++) {
                int mb = wr*32 + i*16 + g;
                a[i][0] = As[buf][mb    ][kp + tg];
                a[i][1] = As[buf][mb + 8][kp + tg];
                a[i][2] = As[buf][mb    ][kp + 4 + tg];
                a[i][3] = As[buf][mb + 8][kp + 4 + tg];
            }
            uint32_t b[4][2];
            #pragma unroll
            for (int j = 0; j < 4; j++) {
                int nb = wc*32 + j*8 + g;
                b[j][0] = Bs[buf][nb][kp + tg];
                b[j][1] = Bs[buf][nb][kp + 4 + tg];
            }
            #pragma unroll
            for (int i = 0; i < 2; i++)
                #pragma unroll
                for (int j = 0; j < 4; j++)
                    mma_f16(acc[i][j], a[i][0], a[i][1], a[i][2], a[i][3],
                            b[j][0], b[j][1]);
        }
        if (!more) break;
        buf ^= 1;
        stsAll(buf);
        __syncthreads();
    }

    // ---- epilogue ----
    #pragma unroll
    for (int i = 0; i < 2; i++) {
        #pragma unroll
        for (int j = 0; j < 4; j++) {
            int r0 = rowBase + wr*32 + i*16 + g;
            int c0 = colBase + wc*32 + j*8 + tg*2;
            #pragma unroll
            for (int e = 0; e < 4; e++) {
                int row = r0 + ((e >> 1) ? 8 : 0);
                int col = c0 + (e & 1);
                if (MODE == 0) {
                    float bias = (col < 3072) ? b1[col] : b2[col-3072];
                    g_XALL[(size_t)row*4096 + col] = acc[i][j][e] + bias;
                } else if (row < Mrows) {
                    Cout[(size_t)row*Nn + col] = acc[i][j][e];
                }
            }
        }
    }
}

// ---------------- legacy tf32 path for small attention/head GEMMs ----------------
__device__ __forceinline__ uint32_t f2tf32(float x){
    uint32_t r;
    asm("cvt.rna.tf32.f32 %0, %1;" : "=r"(r) : "f"(x));
    return r;
}
__device__ __forceinline__ void mma_tf32(float c[4],
    uint32_t a0, uint32_t a1, uint32_t a2, uint32_t a3,
    uint32_t b0, uint32_t b1)
{
    asm volatile(
        "mma.sync.aligned.m16n8k8.row.col.f32.tf32.tf32.f32 "
        "{%0,%1,%2,%3}, {%4,%5,%6,%7}, {%8,%9}, {%0,%1,%2,%3};"
        : "+f"(c[0]), "+f"(c[1]), "+f"(c[2]), "+f"(c[3])
        : "r"(a0), "r"(a1), "r"(a2), "r"(a3), "r"(b0), "r"(b1));
}
__device__ __forceinline__ void sts_row(uint32_t S[][20], int row, int k4, float4 v){
    uint4 t;
    t.x = f2tf32(v.x); t.y = f2tf32(v.y);
    t.z = f2tf32(v.z); t.w = f2tf32(v.w);
    *(uint4*)&S[row][k4] = t;
}
__device__ __forceinline__ void mma_tile16(float acc[2][4][4],
        const uint32_t As[][20], const uint32_t Bs[][20],
        int wr, int wc, int g, int tg)
{
    #pragma unroll
    for (int ks = 0; ks < 16; ks += 8) {
        uint32_t a[2][4];
        #pragma unroll
        for (int i = 0; i < 2; i++) {
            int mb = wr*32 + i*16 + g;
            a[i][0] = As[mb    ][ks + tg];
            a[i][1] = As[mb + 8][ks + tg];
            a[i][2] = As[mb    ][ks + 4 + tg];
            a[i][3] = As[mb + 8][ks + 4 + tg];
        }
        uint32_t b[4][2];
        #pragma unroll
        for (int j = 0; j < 4; j++) {
            int nb = wc*32 + j*8 + g;
            b[j][0] = Bs[nb][ks + tg];
            b[j][1] = Bs[nb][ks + 4 + tg];
        }
        #pragma unroll
        for (int i = 0; i < 2; i++)
            #pragma unroll
            for (int j = 0; j < 4; j++)
                mma_tf32(acc[i][j], a[i][0], a[i][1], a[i][2], a[i][3],
                         b[j][0], b[j][1]);
    }
}

template<bool BT, int ACT>
__global__ __launch_bounds__(128) void gemm_s(
    const float* __restrict__ A, const float* __restrict__ B,
    const float* __restrict__ bias, float* __restrict__ C,
    int M, int N, int K, int sA, int sB, int sC)
{
    A += (size_t)blockIdx.z * sA;
    B += (size_t)blockIdx.z * sB;
    C += (size_t)blockIdx.z * sC;

    __shared__ uint32_t As[2][64][20];
    __shared__ uint32_t Bs[2][64][20];
    const int tid  = threadIdx.x;
    const int lane = tid & 31, warp = tid >> 5;
    const int wr = warp >> 1, wc = warp & 1;
    const int g = lane >> 2, tg = lane & 3;
    const int rowBase = blockIdx.y*64, colBase = blockIdx.x*64;

    float4 rA[2], rB[2];
    auto loadA = [&](int k0){
        #pragma unroll
        for (int it = 0; it < 2; it++) {
            int idx = tid + it*128, row = idx >> 2, k4 = (idx & 3)*4;
            int gr = rowBase + row;
            rA[it] = (gr < M) ? *(const float4*)(A + (size_t)gr*K + k0 + k4)
                              : make_float4(0.f,0.f,0.f,0.f);
        }
    };
    auto loadB = [&](int k0){
        #pragma unroll
        for (int it = 0; it < 2; it++) {
            int idx = tid + it*128;
            if (BT) {
                int row = idx >> 2, k4 = (idx & 3)*4;
                int gn = colBase + row;
                rB[it] = (gn < N) ? *(const float4*)(B + (size_t)gn*K + k0 + k4)
                                  : make_float4(0.f,0.f,0.f,0.f);
            } else {
                int k = idx >> 4, n4 = (idx & 15)*4;
                rB[it] = *(const float4*)(B + (size_t)(k0+k)*N + colBase + n4);
            }
        }
    };
    auto stsAll = [&](int buf){
        #pragma unroll
        for (int it = 0; it < 2; it++) {
            int idx = tid + it*128;
            int rowA = idx >> 2, k4 = (idx & 3)*4;
            sts_row(As[buf], rowA, k4, rA[it]);
            if (BT) {
                sts_row(Bs[buf], rowA, k4, rB[it]);
            } else {
                int k = idx >> 4, n4 = (idx & 15)*4;
                Bs[buf][n4+0][k] = f2tf32(rB[it].x);
                Bs[buf][n4+1][k] = f2tf32(rB[it].y);
                Bs[buf][n4+2][k] = f2tf32(rB[it].z);
                Bs[buf][n4+3][k] = f2tf32(rB[it].w);
            }
        }
    };

    float acc[2][4][4];
    #pragma unroll
    for (int i=0;i<2;i++) for (int j=0;j<4;j++) for (int e=0;e<4;e++) acc[i][j][e]=0.f;

    loadA(0); loadB(0); stsAll(0); __syncthreads();
    int buf = 0;
    for (int k0 = 16; ; k0 += 16) {
        bool more = (k0 < K);
        if (more) { loadA(k0); loadB(k0); }
        mma_tile16(acc, As[buf], Bs[buf], wr, wc, g, tg);
        if (!more) break;
        buf ^= 1;
        stsAll(buf);
        __syncthreads();
    }

    #pragma unroll
    for (int i = 0; i < 2; i++) {
        #pragma unroll
        for (int j = 0; j < 4; j++) {
            int r0 = rowBase + wr*32 + i*16 + g;
            int c0 = colBase + wc*32 + j*8 + tg*2;
            #pragma unroll
            for (int e = 0; e < 4; e++) {
                int row = r0 + ((e >> 1) ? 8 : 0);
                int col = c0 + (e & 1);
                if (row < M && col < N) {
                    float v = acc[i][j][e];
                    if (bias) v += bias[col];
                    if (ACT == 1) v = tanhf(v);
                    else if (ACT == 2) v = fmaxf(v, 0.f);
                    C[(size_t)row*N + col] = v;
                }
            }
        }
    }
}

// ---------------- pointwise kernels ----------------
__global__ void k_embed(const int* __restrict__ lin, const int* __restrict__ rin,
                        const float* __restrict__ emb)
{
    int row = blockIdx.x;
    int t = row >> 9, n = row & 511;
    int tok = t ? rin[n] : lin[n];
    const float4* src = (const float4*)(emb + (size_t)tok*1024);
    float4* dst = (float4*)(g_X + (size_t)row*1024);
    dst[threadIdx.x] = src[threadIdx.x];
}

__global__ void k_leaf(const float* __restrict__ b_iouh)
{
    int gid = blockIdx.x*256 + threadIdx.x;   // 2*256*1024
    int i = gid >> 10, m = gid & 1023;
    int t = i >> 8, j = i & 255;
    int r = d_S.leaf[j];
    size_t x = (size_t)(t*512 + r);
    float ig = g_XALL[x*4096 + m]        + b_iouh[m];
    float og = g_XALL[x*4096 + 1024 + m] + b_iouh[1024 + m];
    float ug = g_XALL[x*4096 + 2048 + m] + b_iouh[2048 + m];
    float c = sigm(ig) * tanhf(ug);
    g_C[x*1024 + m] = c;
    g_H[x*1024 + m] = sigm(og) * tanhf(c);
}

__global__ void k_point(const int* __restrict__ cidx, const float* __restrict__ cmask,
                        int h, int Bn,
                        const float* __restrict__ b_iouh, const float* __restrict__ b_fh)
{
    int gid = blockIdx.x*256 + threadIdx.x;
    if (gid >= 2*Bn*1024) return;
    int i = gid >> 10, m = gid & 1023;
    int t = i >= Bn; int j = i - (t ? Bn : 0);
    int r = d_S.lvl[h][j];
    size_t x = (size_t)(t*512 + r);
    float ig = g_XALL[x*4096 + m]        + g_IOU[(size_t)i*3072 + m]        + b_iouh[m];
    float og = g_XALL[x*4096 + 1024 + m] + g_IOU[(size_t)i*3072 + 1024 + m] + b_iouh[1024 + m];
    float ug = g_XALL[x*4096 + 2048 + m] + g_IOU[(size_t)i*3072 + 2048 + m] + b_iouh[2048 + m];
    float xf = g_XALL[x*4096 + 3072 + m];
    float f0 = sigm(g_FP[(size_t)(2*i  )*1024 + m] + b_fh[m] + xf);
    float f1 = sigm(g_FP[(size_t)(2*i+1)*1024 + m] + b_fh[m] + xf);
    int c0 = cidx[2*r], c1 = cidx[2*r+1];
    float m0 = cmask[2*r], m1 = cmask[2*r+1];
    float cc0 = g_C[((size_t)(t*512 + c0))*1024 + m] * m0;
    float cc1 = g_C[((size_t)(t*512 + c1))*1024 + m] * m1;
    float c = sigm(ig)*tanhf(ug) + f0*cc0 + f1*cc1;
    g_C[x*1024 + m] = c;
    g_H[x*1024 + m] = sigm(og)*tanhf(c);
}

__global__ void k_soft(float* __restrict__ out)
{
    __shared__ float sh[512];
    int b = blockIdx.x;                 // t*16 + hop
    int t = b >> 4, hop = b & 15;
    int n = threadIdx.x;
    float v = g_LOG[(size_t)(t*512 + n)*16 + hop];
    sh[n] = v; __syncthreads();
    for (int s=256; s>0; s>>=1){ if (n < s) sh[n] = fmaxf(sh[n], sh[n+s]); __syncthreads(); }
    float mx = sh[0]; __syncthreads();
    float e = expf(v - mx);
    sh[n] = e; __syncthreads();
    for (int s=256; s>0; s>>=1){ if (n < s) sh[n] += sh[n+s]; __syncthreads(); }
    float a = e / sh[0];
    g_ALPHA[(size_t)b*512 + n] = a;
    out[5 + t*8192 + hop*512 + n] = a;
}

__global__ void k_lat(const float* __restrict__ w_lat, const float* __restrict__ b_lat)
{
    int m = blockIdx.x*256 + threadIdx.x;
    float lv = b_lat[0], rv = b_lat[0];
    #pragma unroll
    for (int h=0; h<16; h++) {
        float w = w_lat[h];
        lv += w * g_LS[h*1024 + m];
        rv += w * g_LS[(16 + h)*1024 + m];
    }
    g_FR[m]        = fabsf(lv - rv);
    g_FR[1024 + m] = lv * rv;
    g_FR[2048 + m] = 0.5f * (lv + rv);
}

__global__ void k_fc(const float* __restrict__ w, const float* __restrict__ bb)
{
    int o = blockIdx.x*8 + (threadIdx.x >> 5);
    int lane = threadIdx.x & 31;
    const float* wr = w + (size_t)o*3072;
    float s = 0.f;
    for (int k=lane; k<3072; k+=32) s += g_FR[k]*wr[k];
    for (int d=16; d; d>>=1) s += __shfl_down_sync(0xffffffffu, s, d);
    if (!lane) { float v = s + bb[o]; g_FC[o] = v > 0.f ? v : 0.01f*v; }
}

__global__ void k_fc2out(const float* __restrict__ w_out, const float* __restrict__ b_out,
                         const float* __restrict__ w_out1, const float* __restrict__ b_out1,
                         float* __restrict__ out)
{
    __shared__ float fc2[256];
    __shared__ float logit[5];
    int tid = threadIdx.x;             // 256
    int wid = tid >> 5, lane = tid & 31;
    for (int it = 0; it < 4; it++) {
        int o = wid*32 + (it << 3) + (lane >> 2);
        float s = 0.f;
        for (int k = (lane & 3); k < 512; k += 4) s += g_FC[k]*w_out[(size_t)o*512 + k];
        s += __shfl_down_sync(0xffffffffu, s, 2);
        s += __shfl_down_sync(0xffffffffu, s, 1);
        if ((lane & 3) == 0) fc2[o] = sigm(s + b_out[o]);
    }
    __syncthreads();
    if (wid < 5) {
        float s = 0.f;
        for (int k = lane; k < 256; k += 32) s += fc2[k]*w_out1[wid*256 + k];
        for (int d = 16; d; d >>= 1) s += __shfl_down_sync(0xffffffffu, s, d);
        if (!lane) logit[wid] = s + b_out1[wid];
    }
    __syncthreads();
    if (tid == 0) {
        float mx = logit[0];
        for (int c=1;c<5;c++) mx = fmaxf(mx, logit[c]);
        float sum = 0.f;
        for (int c=0;c<5;c++) sum += expf(logit[c]-mx);
        float l = logf(sum);
        for (int c=0;c<5;c++) out[c] = logit[c] - mx - l;
    }
}

// ---------------- launch ----------------
extern "C" void kernel_launch(void* const* d_in, const int* in_sizes, int n_in,
                              void* d_out, int out_size)
{
    const int*   linputs    = (const int*)  d_in[0];
    const int*   rinputs    = (const int*)  d_in[1];
    const int*   child_idx  = (const int*)  d_in[2];
    const float* child_mask = (const float*)d_in[3];
    const float* emb        = (const float*)d_in[4];
    const float* w_ioux     = (const float*)d_in[5];
    const float* b_ioux     = (const float*)d_in[6];
    const float* w_iouh     = (const float*)d_in[7];
    const float* b_iouh     = (const float*)d_in[8];
    const float* w_fx       = (const float*)d_in[9];
    const float* b_fx       = (const float*)d_in[10];
    const float* w_fh       = (const float*)d_in[11];
    const float* b_fh       = (const float*)d_in[12];
    const float* ws1        = (const float*)d_in[13];
    const float* ws2        = (const float*)d_in[14];
    const float* wf         = (const float*)d_in[15];
    const float* w_lat      = (const float*)d_in[16];
    const float* b_lat      = (const float*)d_in[17];
    const float* w_fc       = (const float*)d_in[18];
    const float* b_fc       = (const float*)d_in[19];
    const float* w_out      = (const float*)d_in[20];
    const float* b_out      = (const float*)d_in[21];
    const float* w_out1     = (const float*)d_in[22];
    const float* b_out1     = (const float*)d_in[23];
    float* out = (float*)d_out;

    float *pH, *pHB, *pLOG, *pALPHA, *pM, *pLS;
    cudaGetSymbolAddress((void**)&pH,     g_H);
    cudaGetSymbolAddress((void**)&pHB,    g_HB);
    cudaGetSymbolAddress((void**)&pLOG,   g_LOG);
    cudaGetSymbolAddress((void**)&pALPHA, g_ALPHA);
    cudaGetSymbolAddress((void**)&pM,     g_Mm);
    cudaGetSymbolAddress((void**)&pLS,    g_LS);

    // 1) embedding gather
    k_embed<<<1024, 256>>>(linputs, rinputs, emb);

    // 2) fused input projections (fp16 MMA): M=1024, N=4096, K=1024
    gemm_h<0><<<dim3(64, 8, 1), 256>>>(w_ioux, w_fx, b_ioux, b_fx,
                                       nullptr, nullptr, 0, 0);

    // 3) leaves
    k_leaf<<<2048, 256>>>(b_iouh);

    // 4) internal levels (fp16 MMA fused iou+f GEMM, then pointwise)
    for (int h = 1; h <= 15; h++) {
        int B = SCHED.cnt[h];
        if (B == 0) continue;
        int ny = (4*B + 127)/128; if (ny < 1) ny = 1;
        gemm_h<1><<<dim3(48, ny, 2), 256>>>(w_iouh, w_fh, nullptr, nullptr,
                                            child_idx, child_mask, h, B);
        k_point<<<(2*B*1024 + 255)/256, 256>>>(child_idx, child_mask, h, B, b_iouh, b_fh);
    }

    // 5) attention (tf32)
    gemm_s<true,1><<<dim3(4,16,1), 128>>>(pH, ws1, nullptr, pHB,
                                          1024, 256, 1024, 0, 0, 0);
    gemm_s<true,0><<<dim3(1,16,1), 128>>>(pHB, ws2, nullptr, pLOG,
                                          1024, 16, 256, 0, 0, 0);
    k_soft<<<32, 512>>>(out);
    gemm_s<false,0><<<dim3(16,1,2), 128>>>(pALPHA, pH, nullptr, pM,
                                           16, 1024, 512, 16*512, 512*1024, 16*1024);

    // 6) head
    gemm_s<false,2><<<dim3(16,1,1), 128>>>(pM, wf, nullptr, pLS,
                                           32, 1024, 1024, 0, 0, 0);
    k_lat<<<4, 256>>>(w_lat, b_lat);
    k_fc<<<64, 256>>>(w_fc, b_fc);
    k_fc2out<<<1, 256>>>(w_out, b_out, w_out1, b_out1, out);
}

// round 7
// speedup vs baseline: 3.1593x; 1.1269x over previous
#include <cuda_runtime.h>
#include <cuda_fp16.h>
#include <math.h>
#include <stdint.h>

// ---------------- static device scratch ----------------
__device__ __align__(16) float g_XALL[2*512*4096];   // [iou(3072) | f(1024)] per row
__device__ __align__(16) float g_H[2*512*1024];
__device__ __align__(16) float g_C[2*512*1024];
__device__ __align__(16) float g_IOU[256*3072];
__device__ __align__(16) float g_FP[512*1024];
__device__ __align__(16) float g_HB[1024*256];
__device__ __align__(16) float g_LOG[1024*16];
__device__ __align__(16) float g_ALPHA[2*16*512];
__device__ __align__(16) float g_Mm[32*1024];
__device__ __align__(16) float g_LS[32*1024];
__device__ __align__(16) float g_FR[3072];
__device__ __align__(16) float g_FC[512];
// half-precision operand copies
__device__ __align__(16) __half g_Wx[4096*1024];     // [w_ioux rows | w_fx rows]
__device__ __align__(16) __half g_Wiouh[3072*1024];
__device__ __align__(16) __half g_Wfh[1024*1024];
__device__ __align__(16) __half g_Xh[1024*1024];
__device__ __align__(16) __half g_Hh[2*512*1024];

// ---------------- compile-time tree schedule (N=512 heap, DFS post-order) ----------------
struct Sched {
    int leaf[256];
    int cnt[16];
    int lvl[16][128];
};

constexpr Sched make_sched() {
    Sched s{};
    int order[512] = {}; int rankOf[512] = {}; int height[512] = {};
    int stN[64] = {}; int stP[64] = {};
    int sp = 1, cnt = 0;
    stN[0] = 0; stP[0] = 0;
    while (sp) {
        int j = stN[sp-1], p = stP[sp-1];
        if (p < 2) {
            stP[sp-1] = p + 1;
            int c = 2*j + 1 + p;
            if (c < 512) { stN[sp] = c; stP[sp] = 0; sp++; }
        } else { order[cnt] = j; rankOf[j] = cnt; cnt++; sp--; }
    }
    int nleaf = 0;
    for (int r = 0; r < 512; r++) {
        int j = order[r]; int h = 0;
        for (int k = 0; k < 2; k++) {
            int c = 2*j + 1 + k;
            if (c < 512) { int hh = height[rankOf[c]] + 1; if (hh > h) h = hh; }
        }
        height[r] = h;
        if (h == 0) s.leaf[nleaf++] = r;
        else        s.lvl[h][s.cnt[h]++] = r;
    }
    return s;
}

constexpr Sched SCHED = make_sched();
__device__ const Sched d_S = make_sched();

__device__ __forceinline__ float sigm(float x){ return 1.f/(1.f+expf(-x)); }

__device__ __forceinline__ uint2 f4_to_h4(float4 v){
    __half2 p0 = __floats2half2_rn(v.x, v.y);
    __half2 p1 = __floats2half2_rn(v.z, v.w);
    uint2 r; r.x = *(uint32_t*)&p0; r.y = *(uint32_t*)&p1;
    return r;
}

__device__ __forceinline__ uint32_t smem_u32(const void* p){
    uint32_t a;
    asm("{ .reg .u64 t; cvta.to.shared.u64 t, %1; cvt.u32.u64 %0, t; }" : "=r"(a) : "l"(p));
    return a;
}
__device__ __forceinline__ void cpa16(uint32_t dst, const void* src){
    asm volatile("cp.async.cg.shared.global [%0], [%1], 16;" :: "r"(dst), "l"(src));
}

__device__ __forceinline__ void mma_f16(float c[4],
    uint32_t a0, uint32_t a1, uint32_t a2, uint32_t a3,
    uint32_t b0, uint32_t b1)
{
    asm volatile(
        "mma.sync.aligned.m16n8k16.row.col.f32.f16.f16.f32 "
        "{%0,%1,%2,%3}, {%4,%5,%6,%7}, {%8,%9}, {%0,%1,%2,%3};"
        : "+f"(c[0]), "+f"(c[1]), "+f"(c[2]), "+f"(c[3])
        : "r"(a0), "r"(a1), "r"(a2), "r"(a3), "r"(b0), "r"(b1));
}

// ---------------- weight pre-conversion (fp32 -> half), flat ----------------
__global__ void k_cvtW(const float* __restrict__ w_ioux, const float* __restrict__ w_fx,
                       const float* __restrict__ w_iouh, const float* __restrict__ w_fh)
{
    int i = blockIdx.x*256 + threadIdx.x;         // 2,097,152 float4 groups
    const float4* src; uint2* dst;
    if (i < 786432)       { src = (const float4*)w_ioux + i;            dst = (uint2*)g_Wx + i; }
    else if (i < 1048576) { int j = i -  786432; src = (const float4*)w_fx   + j; dst = (uint2*)g_Wx + 786432 + j; }
    else if (i < 1835008) { int j = i - 1048576; src = (const float4*)w_iouh + j; dst = (uint2*)g_Wiouh + j; }
    else                  { int j = i - 1835008; src = (const float4*)w_fh   + j; dst = (uint2*)g_Wfh + j; }
    *dst = f4_to_h4(*src);
}

// ---------------- fp16 cp.async-pipelined GEMM, 128x64 tile, k-chunk 32, 3 stages ----
// MODE 0: A = g_Xh (M=1024), B = g_Wx (N=4096), C = g_XALL + split bias
// MODE 1: per-level; z = blockIdx.z:
//         z=0: A row = masked child-H sum  (M=2Bn), B=g_Wiouh (N=3072), C=g_IOU
//         z=1: A row = single masked child (M=4Bn), B=g_Wfh   (N=1024), C=g_FP
template<int MODE>
__global__ __launch_bounds__(256)
void gemm_h(const float* __restrict__ b1, const float* __restrict__ b2,
            const int* __restrict__ cidx, const float* __restrict__ cmask,
            int h, int Bn)
{
    int Mrows, Nn, z = 0;
    const __half* Bw;
    float* Cout;
    if (MODE == 0) {
        Mrows = 1024; Nn = 4096; Bw = g_Wx; Cout = g_XALL;
    } else {
        z = blockIdx.z;
        Mrows = z ? 4*Bn : 2*Bn;
        Nn    = z ? 1024 : 3072;
        Bw    = z ? g_Wfh : g_Wiouh;
        Cout  = z ? g_FP : g_IOU;
    }
    const int rowBase = blockIdx.y * 128;
    const int colBase = blockIdx.x * 64;
    if (rowBase >= Mrows || colBase >= Nn) return;

    __shared__ uint32_t SA[3][128][20];   // 32 halfs used per row, 80B stride
    __shared__ uint32_t SB[3][64][20];

    const int tid  = threadIdx.x;
    const int lane = tid & 31, warp = tid >> 5;
    const int wr = warp >> 1;            // 0..3
    const int wc = warp & 1;             // 0..1
    const int g  = lane >> 2, tg = lane & 3;

    const uint32_t baA = smem_u32(&SA[0][0][0]);
    const uint32_t baB = smem_u32(&SB[0][0][0]);

    // ---- per-thread gather setup (MODE 1 A rows; fixed across k) ----
    const __half* aptr0[2]; const __half* aptr1[2];
    __half2 am0[2], am1[2]; bool avalid[2]; int arow[2], ach[2];
    #pragma unroll
    for (int it = 0; it < 2; it++) {
        int idx = tid + (it << 8);
        int row = idx >> 2, ch = idx & 3;
        arow[it] = row; ach[it] = ch;
        int gr = rowBase + row;
        avalid[it] = false;
        if (MODE == 1 && gr < Mrows) {
            avalid[it] = true;
            if (z == 0) {
                int t = gr >= Bn; int j = gr - (t ? Bn : 0);
                int r = d_S.lvl[h][j];
                aptr0[it] = g_Hh + ((size_t)(t*512 + cidx[2*r  ]))*1024 + ch*8;
                aptr1[it] = g_Hh + ((size_t)(t*512 + cidx[2*r+1]))*1024 + ch*8;
                am0[it] = __float2half2_rn(cmask[2*r]);
                am1[it] = __float2half2_rn(cmask[2*r+1]);
            } else {
                int t = gr >= 2*Bn; int rem = gr - (t ? 2*Bn : 0);
                int j = rem >> 1, ck = rem & 1;
                int r = d_S.lvl[h][j];
                aptr0[it] = g_Hh + ((size_t)(t*512 + cidx[2*r+ck]))*1024 + ch*8;
                aptr1[it] = aptr0[it];
                am0[it] = __float2half2_rn(cmask[2*r+ck]);
                am1[it] = __float2half2_rn(0.f);
            }
        }
    }

    // ---- zero-fill invalid A rows in all stages (persist across rotation) ----
    if (MODE == 1) {
        const uint4 zz = make_uint4(0,0,0,0);
        #pragma unroll
        for (int s = 0; s < 3; s++)
            #pragma unroll
            for (int it = 0; it < 2; it++)
                if (!avalid[it]) *(uint4*)&SA[s][arow[it]][ach[it]*4] = zz;
    }

    auto issue = [&](int stage, int k0){
        { // B: 64 rows x 4 chunks = 256 -> 1 per thread
            int row = tid >> 2, ch = tid & 3;
            cpa16(baB + ((stage*64 + row)*20 + ch*4)*4,
                  Bw + (size_t)(colBase + row)*1024 + k0 + ch*8);
        }
        if (MODE == 0) {
            #pragma unroll
            for (int it = 0; it < 2; it++) {
                int idx = tid + (it << 8);
                int row = idx >> 2, ch = idx & 3;
                cpa16(baA + ((stage*128 + row)*20 + ch*4)*4,
                      g_Xh + (size_t)(rowBase + row)*1024 + k0 + ch*8);
            }
        }
        asm volatile("cp.async.commit_group;" ::: "memory");
    };

    float acc[2][4][4];
    #pragma unroll
    for (int i=0;i<2;i++) for (int j=0;j<4;j++) for (int e=0;e<4;e++) acc[i][j][e]=0.f;

    // MODE 1: manual A for stages 0,1 (prologue)
    uint4 va[2];
    auto gatherA = [&](int k0){
        #pragma unroll
        for (int it = 0; it < 2; it++) {
            if (!avalid[it]) continue;
            uint4 u0 = *(const uint4*)(aptr0[it] + k0);
            uint4 u1 = *(const uint4*)(aptr1[it] + k0);
            __half2* a = (__half2*)&u0; __half2* b = (__half2*)&u1;
            uint4 r;
            __half2* o = (__half2*)&r;
            #pragma unroll
            for (int w = 0; w < 4; w++)
                o[w] = (MODE==1 && z==0) ? __hfma2(b[w], am1[it], __hmul2(a[w], am0[it]))
                                         : __hmul2(a[w], am0[it]);
            va[it] = r;
        }
    };
    auto stsA = [&](int stage){
        #pragma unroll
        for (int it = 0; it < 2; it++)
            if (avalid[it]) *(uint4*)&SA[stage][arow[it]][ach[it]*4] = va[it];
    };

    if (MODE == 1) { gatherA(0);  stsA(0); }
    issue(0, 0);
    if (MODE == 1) { gatherA(32); stsA(1); }
    issue(1, 32);

    for (int c = 0; c < 32; c++) {
        const int stage = c % 3;
        const int kn = (c + 2) * 32;
        const int nst = (c + 2) % 3;
        if (MODE == 1 && kn < 1024) gatherA(kn);
        if (kn < 1024) { asm volatile("cp.async.wait_group 1;" ::: "memory"); }
        else           { asm volatile("cp.async.wait_group 0;" ::: "memory"); }
        __syncthreads();
        if (kn < 1024) {
            if (MODE == 1) stsA(nst);
            issue(nst, kn);
        }
        // compute on stage: 2 k16 steps
        #pragma unroll
        for (int s = 0; s < 2; s++) {
            const int kp = s*8;
            uint32_t a[2][4];
            #pragma unroll
            for (int i = 0; i < 2; i++) {
                int mb = wr*32 + i*16 + g;
                a[i][0] = SA[stage][mb    ][kp + tg];
                a[i][1] = SA[stage][mb + 8][kp + tg];
                a[i][2] = SA[stage][mb    ][kp + 4 + tg];
                a[i][3] = SA[stage][mb + 8][kp + 4 + tg];
            }
            uint32_t b[4][2];
            #pragma unroll
            for (int j = 0; j < 4; j++) {
                int nb = wc*32 + j*8 + g;
                b[j][0] = SB[stage][nb][kp + tg];
                b[j][1] = SB[stage][nb][kp + 4 + tg];
            }
            #pragma unroll
            for (int i = 0; i < 2; i++)
                #pragma unroll
                for (int j = 0; j < 4; j++)
                    mma_f16(acc[i][j], a[i][0], a[i][1], a[i][2], a[i][3],
                            b[j][0], b[j][1]);
        }
        __syncthreads();
    }

    // ---- epilogue ----
    #pragma unroll
    for (int i = 0; i < 2; i++) {
        #pragma unroll
        for (int j = 0; j < 4; j++) {
            int r0 = rowBase + wr*32 + i*16 + g;
            int c0 = colBase + wc*32 + j*8 + tg*2;
            #pragma unroll
            for (int e = 0; e < 4; e++) {
                int row = r0 + ((e >> 1) ? 8 : 0);
                int col = c0 + (e & 1);
                if (MODE == 0) {
                    float bias = (col < 3072) ? b1[col] : b2[col-3072];
                    g_XALL[(size_t)row*4096 + col] = acc[i][j][e] + bias;
                } else if (row < Mrows) {
                    Cout[(size_t)row*Nn + col] = acc[i][j][e];
                }
            }
        }
    }
}

// ---------------- legacy tf32 path for small attention/head GEMMs ----------------
__device__ __forceinline__ uint32_t f2tf32(float x){
    uint32_t r;
    asm("cvt.rna.tf32.f32 %0, %1;" : "=r"(r) : "f"(x));
    return r;
}
__device__ __forceinline__ void mma_tf32(float c[4],
    uint32_t a0, uint32_t a1, uint32_t a2, uint32_t a3,
    uint32_t b0, uint32_t b1)
{
    asm volatile(
        "mma.sync.aligned.m16n8k8.row.col.f32.tf32.tf32.f32 "
        "{%0,%1,%2,%3}, {%4,%5,%6,%7}, {%8,%9}, {%0,%1,%2,%3};"
        : "+f"(c[0]), "+f"(c[1]), "+f"(c[2]), "+f"(c[3])
        : "r"(a0), "r"(a1), "r"(a2), "r"(a3), "r"(b0), "r"(b1));
}
__device__ __forceinline__ void sts_row(uint32_t S[][20], int row, int k4, float4 v){
    uint4 t;
    t.x = f2tf32(v.x); t.y = f2tf32(v.y);
    t.z = f2tf32(v.z); t.w = f2tf32(v.w);
    *(uint4*)&S[row][k4] = t;
}
__device__ __forceinline__ void mma_tile16(float acc[2][4][4],
        const uint32_t As[][20], const uint32_t Bs[][20],
        int wr, int wc, int g, int tg)
{
    #pragma unroll
    for (int ks = 0; ks < 16; ks += 8) {
        uint32_t a[2][4];
        #pragma unroll
        for (int i = 0; i < 2; i++) {
            int mb = wr*32 + i*16 + g;
            a[i][0] = As[mb    ][ks + tg];
            a[i][1] = As[mb + 8][ks + tg];
            a[i][2] = As[mb    ][ks + 4 + tg];
            a[i][3] = As[mb + 8][ks + 4 + tg];
        }
        uint32_t b[4][2];
        #pragma unroll
        for (int j = 0; j < 4; j++) {
            int nb = wc*32 + j*8 + g;
            b[j][0] = Bs[nb][ks + tg];
            b[j][1] = Bs[nb][ks + 4 + tg];
        }
        #pragma unroll
        for (int i = 0; i < 2; i++)
            #pragma unroll
            for (int j = 0; j < 4; j++)
                mma_tf32(acc[i][j], a[i][0], a[i][1], a[i][2], a[i][3],
                         b[j][0], b[j][1]);
    }
}

template<bool BT, int ACT>
__global__ __launch_bounds__(128) void gemm_s(
    const float* __restrict__ A, const float* __restrict__ B,
    const float* __restrict__ bias, float* __restrict__ C,
    int M, int N, int K, int sA, int sB, int sC)
{
    A += (size_t)blockIdx.z * sA;
    B += (size_t)blockIdx.z * sB;
    C += (size_t)blockIdx.z * sC;

    __shared__ uint32_t As[2][64][20];
    __shared__ uint32_t Bs[2][64][20];
    const int tid  = threadIdx.x;
    const int lane = tid & 31, warp = tid >> 5;
    const int wr = warp >> 1, wc = warp & 1;
    const int g = lane >> 2, tg = lane & 3;
    const int rowBase = blockIdx.y*64, colBase = blockIdx.x*64;

    float4 rA[2], rB[2];
    auto loadA = [&](int k0){
        #pragma unroll
        for (int it = 0; it < 2; it++) {
            int idx = tid + it*128, row = idx >> 2, k4 = (idx & 3)*4;
            int gr = rowBase + row;
            rA[it] = (gr < M) ? *(const float4*)(A + (size_t)gr*K + k0 + k4)
                              : make_float4(0.f,0.f,0.f,0.f);
        }
    };
    auto loadB = [&](int k0){
        #pragma unroll
        for (int it = 0; it < 2; it++) {
            int idx = tid + it*128;
            if (BT) {
                int row = idx >> 2, k4 = (idx & 3)*4;
                int gn = colBase + row;
                rB[it] = (gn < N) ? *(const float4*)(B + (size_t)gn*K + k0 + k4)
                                  : make_float4(0.f,0.f,0.f,0.f);
            } else {
                int k = idx >> 4, n4 = (idx & 15)*4;
                rB[it] = *(const float4*)(B + (size_t)(k0+k)*N + colBase + n4);
            }
        }
    };
    auto stsAll = [&](int buf){
        #pragma unroll
        for (int it = 0; it < 2; it++) {
            int idx = tid + it*128;
            int rowA = idx >> 2, k4 = (idx & 3)*4;
            sts_row(As[buf], rowA, k4, rA[it]);
            if (BT) {
                sts_row(Bs[buf], rowA, k4, rB[it]);
            } else {
                int k = idx >> 4, n4 = (idx & 15)*4;
                Bs[buf][n4+0][k] = f2tf32(rB[it].x);
                Bs[buf][n4+1][k] = f2tf32(rB[it].y);
                Bs[buf][n4+2][k] = f2tf32(rB[it].z);
                Bs[buf][n4+3][k] = f2tf32(rB[it].w);
            }
        }
    };

    float acc[2][4][4];
    #pragma unroll
    for (int i=0;i<2;i++) for (int j=0;j<4;j++) for (int e=0;e<4;e++) acc[i][j][e]=0.f;

    loadA(0); loadB(0); stsAll(0); __syncthreads();
    int buf = 0;
    for (int k0 = 16; ; k0 += 16) {
        bool more = (k0 < K);
        if (more) { loadA(k0); loadB(k0); }
        mma_tile16(acc, As[buf], Bs[buf], wr, wc, g, tg);
        if (!more) break;
        buf ^= 1;
        stsAll(buf);
        __syncthreads();
    }

    #pragma unroll
    for (int i = 0; i < 2; i++) {
        #pragma unroll
        for (int j = 0; j < 4; j++) {
            int r0 = rowBase + wr*32 + i*16 + g;
            int c0 = colBase + wc*32 + j*8 + tg*2;
            #pragma unroll
            for (int e = 0; e < 4; e++) {
                int row = r0 + ((e >> 1) ? 8 : 0);
                int col = c0 + (e & 1);
                if (row < M && col < N) {
                    float v = acc[i][j][e];
                    if (bias) v += bias[col];
                    if (ACT == 1) v = tanhf(v);
                    else if (ACT == 2) v = fmaxf(v, 0.f);
                    C[(size_t)row*N + col] = v;
                }
            }
        }
    }
}

// ---------------- pointwise kernels ----------------
__global__ void k_embed(const int* __restrict__ lin, const int* __restrict__ rin,
                        const float* __restrict__ emb)
{
    int row = blockIdx.x;
    int t = row >> 9, n = row & 511;
    int tok = t ? rin[n] : lin[n];
    float4 v = ((const float4*)(emb + (size_t)tok*1024))[threadIdx.x];
    ((uint2*)(g_Xh + (size_t)row*1024))[threadIdx.x] = f4_to_h4(v);
}

__global__ void k_leaf(const float* __restrict__ b_iouh)
{
    int gid = blockIdx.x*256 + threadIdx.x;   // 2*256*1024
    int i = gid >> 10, m = gid & 1023;
    int t = i >> 8, j = i & 255;
    int r = d_S.leaf[j];
    size_t x = (size_t)(t*512 + r);
    float ig = g_XALL[x*4096 + m]        + b_iouh[m];
    float og = g_XALL[x*4096 + 1024 + m] + b_iouh[1024 + m];
    float ug = g_XALL[x*4096 + 2048 + m] + b_iouh[2048 + m];
    float c = sigm(ig) * tanhf(ug);
    float hv = sigm(og) * tanhf(c);
    g_C[x*1024 + m] = c;
    g_H[x*1024 + m] = hv;
    g_Hh[x*1024 + m] = __float2half(hv);
}

__global__ void k_point(const int* __restrict__ cidx, const float* __restrict__ cmask,
                        int h, int Bn,
                        const float* __restrict__ b_iouh, const float* __restrict__ b_fh)
{
    int gid = blockIdx.x*256 + threadIdx.x;
    if (gid >= 2*Bn*1024) return;
    int i = gid >> 10, m = gid & 1023;
    int t = i >= Bn; int j = i - (t ? Bn : 0);
    int r = d_S.lvl[h][j];
    size_t x = (size_t)(t*512 + r);
    float ig = g_XALL[x*4096 + m]        + g_IOU[(size_t)i*3072 + m]        + b_iouh[m];
    float og = g_XALL[x*4096 + 1024 + m] + g_IOU[(size_t)i*3072 + 1024 + m] + b_iouh[1024 + m];
    float ug = g_XALL[x*4096 + 2048 + m] + g_IOU[(size_t)i*3072 + 2048 + m] + b_iouh[2048 + m];
    float xf = g_XALL[x*4096 + 3072 + m];
    float f0 = sigm(g_FP[(size_t)(2*i  )*1024 + m] + b_fh[m] + xf);
    float f1 = sigm(g_FP[(size_t)(2*i+1)*1024 + m] + b_fh[m] + xf);
    int c0 = cidx[2*r], c1 = cidx[2*r+1];
    float m0 = cmask[2*r], m1 = cmask[2*r+1];
    float cc0 = g_C[((size_t)(t*512 + c0))*1024 + m] * m0;
    float cc1 = g_C[((size_t)(t*512 + c1))*1024 + m] * m1;
    float c = sigm(ig)*tanhf(ug) + f0*cc0 + f1*cc1;
    float hv = sigm(og)*tanhf(c);
    g_C[x*1024 + m] = c;
    g_H[x*1024 + m] = hv;
    g_Hh[x*1024 + m] = __float2half(hv);
}

__global__ void k_soft(float* __restrict__ out)
{
    __shared__ float sh[512];
    int b = blockIdx.x;                 // t*16 + hop
    int t = b >> 4, hop = b & 15;
    int n = threadIdx.x;
    float v = g_LOG[(size_t)(t*512 + n)*16 + hop];
    sh[n] = v; __syncthreads();
    for (int s=256; s>0; s>>=1){ if (n < s) sh[n] = fmaxf(sh[n], sh[n+s]); __syncthreads(); }
    float mx = sh[0]; __syncthreads();
    float e = expf(v - mx);
    sh[n] = e; __syncthreads();
    for (int s=256; s>0; s>>=1){ if (n < s) sh[n] += sh[n+s]; __syncthreads(); }
    float a = e / sh[0];
    g_ALPHA[(size_t)b*512 + n] = a;
    out[5 + t*8192 + hop*512 + n] = a;
}

__global__ void k_lat(const float* __restrict__ w_lat, const float* __restrict__ b_lat)
{
    int m = blockIdx.x*256 + threadIdx.x;
    float lv = b_lat[0], rv = b_lat[0];
    #pragma unroll
    for (int h=0; h<16; h++) {
        float w = w_lat[h];
        lv += w * g_LS[h*1024 + m];
        rv += w * g_LS[(16 + h)*1024 + m];
    }
    g_FR[m]        = fabsf(lv - rv);
    g_FR[1024 + m] = lv * rv;
    g_FR[2048 + m] = 0.5f * (lv + rv);
}

__global__ void k_fc(const float* __restrict__ w, const float* __restrict__ bb)
{
    int o = blockIdx.x*8 + (threadIdx.x >> 5);
    int lane = threadIdx.x & 31;
    const float* wr = w + (size_t)o*3072;
    float s = 0.f;
    for (int k=lane; k<3072; k+=32) s += g_FR[k]*wr[k];
    for (int d=16; d; d>>=1) s += __shfl_down_sync(0xffffffffu, s, d);
    if (!lane) { float v = s + bb[o]; g_FC[o] = v > 0.f ? v : 0.01f*v; }
}

__global__ void k_fc2out(const float* __restrict__ w_out, const float* __restrict__ b_out,
                         const float* __restrict__ w_out1, const float* __restrict__ b_out1,
                         float* __restrict__ out)
{
    __shared__ float fc2[256];
    __shared__ float logit[5];
    int tid = threadIdx.x;             // 256
    int wid = tid >> 5, lane = tid & 31;
    for (int it = 0; it < 4; it++) {
        int o = wid*32 + (it << 3) + (lane >> 2);
        float s = 0.f;
        for (int k = (lane & 3); k < 512; k += 4) s += g_FC[k]*w_out[(size_t)o*512 + k];
        s += __shfl_down_sync(0xffffffffu, s, 2);
        s += __shfl_down_sync(0xffffffffu, s, 1);
        if ((lane & 3) == 0) fc2[o] = sigm(s + b_out[o]);
    }
    __syncthreads();
    if (wid < 5) {
        float s = 0.f;
        for (int k = lane; k < 256; k += 32) s += fc2[k]*w_out1[wid*256 + k];
        for (int d = 16; d; d >>= 1) s += __shfl_down_sync(0xffffffffu, s, d);
        if (!lane) logit[wid] = s + b_out1[wid];
    }
    __syncthreads();
    if (tid == 0) {
        float mx = logit[0];
        for (int c=1;c<5;c++) mx = fmaxf(mx, logit[c]);
        float sum = 0.f;
        for (int c=0;c<5;c++) sum += expf(logit[c]-mx);
        float l = logf(sum);
        for (int c=0;c<5;c++) out[c] = logit[c] - mx - l;
    }
}

// ---------------- launch ----------------
extern "C" void kernel_launch(void* const* d_in, const int* in_sizes, int n_in,
                              void* d_out, int out_size)
{
    const int*   linputs    = (const int*)  d_in[0];
    const int*   rinputs    = (const int*)  d_in[1];
    const int*   child_idx  = (const int*)  d_in[2];
    const float* child_mask = (const float*)d_in[3];
    const float* emb        = (const float*)d_in[4];
    const float* w_ioux     = (const float*)d_in[5];
    const float* b_ioux     = (const float*)d_in[6];
    const float* w_iouh     = (const float*)d_in[7];
    const float* b_iouh     = (const float*)d_in[8];
    const float* w_fx       = (const float*)d_in[9];
    const float* b_fx       = (const float*)d_in[10];
    const float* w_fh       = (const float*)d_in[11];
    const float* b_fh       = (const float*)d_in[12];
    const float* ws1        = (const float*)d_in[13];
    const float* ws2        = (const float*)d_in[14];
    const float* wf         = (const float*)d_in[15];
    const float* w_lat      = (const float*)d_in[16];
    const float* b_lat      = (const float*)d_in[17];
    const float* w_fc       = (const float*)d_in[18];
    const float* b_fc       = (const float*)d_in[19];
    const float* w_out      = (const float*)d_in[20];
    const float* b_out      = (const float*)d_in[21];
    const float* w_out1     = (const float*)d_in[22];
    const float* b_out1     = (const float*)d_in[23];
    float* out = (float*)d_out;

    float *pH, *pHB, *pLOG, *pALPHA, *pM, *pLS;
    cudaGetSymbolAddress((void**)&pH,     g_H);
    cudaGetSymbolAddress((void**)&pHB,    g_HB);
    cudaGetSymbolAddress((void**)&pLOG,   g_LOG);
    cudaGetSymbolAddress((void**)&pALPHA, g_ALPHA);
    cudaGetSymbolAddress((void**)&pM,     g_Mm);
    cudaGetSymbolAddress((void**)&pLS,    g_LS);

    // 0) weight conversion to half (independent of embed)
    k_cvtW<<<8192, 256>>>(w_ioux, w_fx, w_iouh, w_fh);

    // 1) embedding gather (half)
    k_embed<<<1024, 256>>>(linputs, rinputs, emb);

    // 2) fused input projections: M=1024, N=4096, K=1024
    gemm_h<0><<<dim3(64, 8, 1), 256>>>(b_ioux, b_fx, nullptr, nullptr, 0, 0);

    // 3) leaves
    k_leaf<<<2048, 256>>>(b_iouh);

    // 4) internal levels
    for (int h = 1; h <= 15; h++) {
        int B = SCHED.cnt[h];
        if (B == 0) continue;
        int ny = (4*B + 127)/128; if (ny < 1) ny = 1;
        gemm_h<1><<<dim3(48, ny, 2), 256>>>(nullptr, nullptr,
                                            child_idx, child_mask, h, B);
        k_point<<<(2*B*1024 + 255)/256, 256>>>(child_idx, child_mask, h, B, b_iouh, b_fh);
    }

    // 5) attention (tf32)
    gemm_s<true,1><<<dim3(4,16,1), 128>>>(pH, ws1, nullptr, pHB,
                                          1024, 256, 1024, 0, 0, 0);
    gemm_s<true,0><<<dim3(1,16,1), 128>>>(pHB, ws2, nullptr, pLOG,
                                          1024, 16, 256, 0, 0, 0);
    k_soft<<<32, 512>>>(out);
    gemm_s<false,0><<<dim3(16,1,2), 128>>>(pALPHA, pH, nullptr, pM,
                                           16, 1024, 512, 16*512, 512*1024, 16*1024);

    // 6) head
    gemm_s<false,2><<<dim3(16,1,1), 128>>>(pM, wf, nullptr, pLS,
                                           32, 1024, 1024, 0, 0, 0);
    k_lat<<<4, 256>>>(w_lat, b_lat);
    k_fc<<<64, 256>>>(w_fc, b_fc);
    k_fc2out<<<1, 256>>>(w_out, b_out, w_out1, b_out1, out);
}

// round 8
// speedup vs baseline: 3.1710x; 1.0037x over previous
#include <cuda_runtime.h>
#include <cuda_fp16.h>
#include <math.h>
#include <stdint.h>

// ---------------- static device scratch ----------------
__device__ __align__(16) float g_XALL[2*512*4096];   // [iou(3072) | f(1024)] per row
__device__ __align__(16) float g_H[2*512*1024];
__device__ __align__(16) float g_C[2*512*1024];
__device__ __align__(16) float g_IOU[256*3072];
__device__ __align__(16) float g_FP[512*1024];
__device__ __align__(16) float g_HB[1024*256];
__device__ __align__(16) float g_LOG[1024*16];
__device__ __align__(16) float g_ALPHA[2*16*512];
__device__ __align__(16) float g_Mm[32*1024];
__device__ __align__(16) float g_LS[32*1024];
__device__ __align__(16) float g_FR[3072];
__device__ __align__(16) float g_FC[512];
// half-precision operand copies
__device__ __align__(16) __half g_Wx[4096*1024];     // [w_ioux rows | w_fx rows]
__device__ __align__(16) __half g_Wiouh[3072*1024];
__device__ __align__(16) __half g_Wfh[1024*1024];
__device__ __align__(16) __half g_Xh[1024*1024];
__device__ __align__(16) __half g_Hh[2*512*1024];

// ---------------- compile-time tree schedule (N=512 heap, DFS post-order) ----------------
struct Sched {
    int leaf[256];
    int cnt[16];
    int lvl[16][128];
};

constexpr Sched make_sched() {
    Sched s{};
    int order[512] = {}; int rankOf[512] = {}; int height[512] = {};
    int stN[64] = {}; int stP[64] = {};
    int sp = 1, cnt = 0;
    stN[0] = 0; stP[0] = 0;
    while (sp) {
        int j = stN[sp-1], p = stP[sp-1];
        if (p < 2) {
            stP[sp-1] = p + 1;
            int c = 2*j + 1 + p;
            if (c < 512) { stN[sp] = c; stP[sp] = 0; sp++; }
        } else { order[cnt] = j; rankOf[j] = cnt; cnt++; sp--; }
    }
    int nleaf = 0;
    for (int r = 0; r < 512; r++) {
        int j = order[r]; int h = 0;
        for (int k = 0; k < 2; k++) {
            int c = 2*j + 1 + k;
            if (c < 512) { int hh = height[rankOf[c]] + 1; if (hh > h) h = hh; }
        }
        height[r] = h;
        if (h == 0) s.leaf[nleaf++] = r;
        else        s.lvl[h][s.cnt[h]++] = r;
    }
    return s;
}

constexpr Sched SCHED = make_sched();
__device__ const Sched d_S = make_sched();

__device__ __forceinline__ float sigm(float x){ return 1.f/(1.f+expf(-x)); }

__device__ __forceinline__ uint2 f4_to_h4(float4 v){
    __half2 p0 = __floats2half2_rn(v.x, v.y);
    __half2 p1 = __floats2half2_rn(v.z, v.w);
    uint2 r; r.x = *(uint32_t*)&p0; r.y = *(uint32_t*)&p1;
    return r;
}

__device__ __forceinline__ uint32_t smem_u32(const void* p){
    uint32_t a;
    asm("{ .reg .u64 t; cvta.to.shared.u64 t, %1; cvt.u32.u64 %0, t; }" : "=r"(a) : "l"(p));
    return a;
}
__device__ __forceinline__ void cpa16(uint32_t dst, const void* src){
    asm volatile("cp.async.cg.shared.global [%0], [%1], 16;" :: "r"(dst), "l"(src));
}

__device__ __forceinline__ void mma_f16(float c[4],
    uint32_t a0, uint32_t a1, uint32_t a2, uint32_t a3,
    uint32_t b0, uint32_t b1)
{
    asm volatile(
        "mma.sync.aligned.m16n8k16.row.col.f32.f16.f16.f32 "
        "{%0,%1,%2,%3}, {%4,%5,%6,%7}, {%8,%9}, {%0,%1,%2,%3};"
        : "+f"(c[0]), "+f"(c[1]), "+f"(c[2]), "+f"(c[3])
        : "r"(a0), "r"(a1), "r"(a2), "r"(a3), "r"(b0), "r"(b1));
}

// ---------------- weight pre-conversion (fp32 -> half), flat ----------------
__global__ void k_cvtW(const float* __restrict__ w_ioux, const float* __restrict__ w_fx,
                       const float* __restrict__ w_iouh, const float* __restrict__ w_fh)
{
    int i = blockIdx.x*256 + threadIdx.x;         // 2,097,152 float4 groups
    const float4* src; uint2* dst;
    if (i < 786432)       { src = (const float4*)w_ioux + i;            dst = (uint2*)g_Wx + i; }
    else if (i < 1048576) { int j = i -  786432; src = (const float4*)w_fx   + j; dst = (uint2*)g_Wx + 786432 + j; }
    else if (i < 1835008) { int j = i - 1048576; src = (const float4*)w_iouh + j; dst = (uint2*)g_Wiouh + j; }
    else                  { int j = i - 1835008; src = (const float4*)w_fh   + j; dst = (uint2*)g_Wfh + j; }
    *dst = f4_to_h4(*src);
}

// ---------------- fp16 cp.async-pipelined GEMM, 128x64 tile, k-chunk 32, 3 stages ----
// MODE 0: A = g_Xh (M=1024), B = g_Wx (N=4096), C = g_XALL + split bias
// MODE 1: per-level; z = blockIdx.z:
//         z=0: A row = masked child-H sum  (M=2Bn), B=g_Wiouh (N=3072), C=g_IOU
//         z=1: A row = single masked child (M=4Bn), B=g_Wfh   (N=1024), C=g_FP
template<int MODE>
__global__ __launch_bounds__(256)
void gemm_h(const float* __restrict__ b1, const float* __restrict__ b2,
            const int* __restrict__ cidx, const float* __restrict__ cmask,
            int h, int Bn)
{
    int Mrows, Nn, z = 0;
    const __half* Bw;
    float* Cout;
    if (MODE == 0) {
        Mrows = 1024; Nn = 4096; Bw = g_Wx; Cout = g_XALL;
    } else {
        z = blockIdx.z;
        Mrows = z ? 4*Bn : 2*Bn;
        Nn    = z ? 1024 : 3072;
        Bw    = z ? g_Wfh : g_Wiouh;
        Cout  = z ? g_FP : g_IOU;
    }
    const int rowBase = blockIdx.y * 128;
    const int colBase = blockIdx.x * 64;
    if (rowBase >= Mrows || colBase >= Nn) return;

    __shared__ uint32_t SA[3][128][20];   // 32 halfs used per row, 80B stride
    __shared__ uint32_t SB[3][64][20];

    const int tid  = threadIdx.x;
    const int lane = tid & 31, warp = tid >> 5;
    const int wr = warp >> 1;            // 0..3
    const int wc = warp & 1;             // 0..1
    const int g  = lane >> 2, tg = lane & 3;

    const uint32_t baA = smem_u32(&SA[0][0][0]);
    const uint32_t baB = smem_u32(&SB[0][0][0]);

    // ---- per-thread gather setup (MODE 1 A rows; fixed across k) ----
    const __half* aptr0[2]; const __half* aptr1[2];
    __half2 am0[2], am1[2]; bool avalid[2]; int arow[2], ach[2];
    #pragma unroll
    for (int it = 0; it < 2; it++) {
        int idx = tid + (it << 8);
        int row = idx >> 2, ch = idx & 3;
        arow[it] = row; ach[it] = ch;
        int gr = rowBase + row;
        avalid[it] = false;
        if (MODE == 1 && gr < Mrows) {
            avalid[it] = true;
            if (z == 0) {
                int t = gr >= Bn; int j = gr - (t ? Bn : 0);
                int r = d_S.lvl[h][j];
                aptr0[it] = g_Hh + ((size_t)(t*512 + cidx[2*r  ]))*1024 + ch*8;
                aptr1[it] = g_Hh + ((size_t)(t*512 + cidx[2*r+1]))*1024 + ch*8;
                am0[it] = __float2half2_rn(cmask[2*r]);
                am1[it] = __float2half2_rn(cmask[2*r+1]);
            } else {
                int t = gr >= 2*Bn; int rem = gr - (t ? 2*Bn : 0);
                int j = rem >> 1, ck = rem & 1;
                int r = d_S.lvl[h][j];
                aptr0[it] = g_Hh + ((size_t)(t*512 + cidx[2*r+ck]))*1024 + ch*8;
                aptr1[it] = aptr0[it];
                am0[it] = __float2half2_rn(cmask[2*r+ck]);
                am1[it] = __float2half2_rn(0.f);
            }
        }
    }

    // ---- zero-fill invalid A rows in all stages (persist across rotation) ----
    if (MODE == 1) {
        const uint4 zz = make_uint4(0,0,0,0);
        #pragma unroll
        for (int s = 0; s < 3; s++)
            #pragma unroll
            for (int it = 0; it < 2; it++)
                if (!avalid[it]) *(uint4*)&SA[s][arow[it]][ach[it]*4] = zz;
    }

    auto issue = [&](int stage, int k0){
        { // B: 64 rows x 4 chunks = 256 -> 1 per thread
            int row = tid >> 2, ch = tid & 3;
            cpa16(baB + ((stage*64 + row)*20 + ch*4)*4,
                  Bw + (size_t)(colBase + row)*1024 + k0 + ch*8);
        }
        if (MODE == 0) {
            #pragma unroll
            for (int it = 0; it < 2; it++) {
                int idx = tid + (it << 8);
                int row = idx >> 2, ch = idx & 3;
                cpa16(baA + ((stage*128 + row)*20 + ch*4)*4,
                      g_Xh + (size_t)(rowBase + row)*1024 + k0 + ch*8);
            }
        }
        asm volatile("cp.async.commit_group;" ::: "memory");
    };

    float acc[2][4][4];
    #pragma unroll
    for (int i=0;i<2;i++) for (int j=0;j<4;j++) for (int e=0;e<4;e++) acc[i][j][e]=0.f;

    // MODE 1: manual A for stages 0,1 (prologue)
    uint4 va[2];
    auto gatherA = [&](int k0){
        #pragma unroll
        for (int it = 0; it < 2; it++) {
            if (!avalid[it]) continue;
            uint4 u0 = *(const uint4*)(aptr0[it] + k0);
            uint4 u1 = *(const uint4*)(aptr1[it] + k0);
            __half2* a = (__half2*)&u0; __half2* b = (__half2*)&u1;
            uint4 r;
            __half2* o = (__half2*)&r;
            #pragma unroll
            for (int w = 0; w < 4; w++)
                o[w] = (MODE==1 && z==0) ? __hfma2(b[w], am1[it], __hmul2(a[w], am0[it]))
                                         : __hmul2(a[w], am0[it]);
            va[it] = r;
        }
    };
    auto stsA = [&](int stage){
        #pragma unroll
        for (int it = 0; it < 2; it++)
            if (avalid[it]) *(uint4*)&SA[stage][arow[it]][ach[it]*4] = va[it];
    };

    if (MODE == 1) { gatherA(0);  stsA(0); }
    issue(0, 0);
    if (MODE == 1) { gatherA(32); stsA(1); }
    issue(1, 32);

    for (int c = 0; c < 32; c++) {
        const int stage = c % 3;
        const int kn = (c + 2) * 32;
        const int nst = (c + 2) % 3;
        if (MODE == 1 && kn < 1024) gatherA(kn);
        if (kn < 1024) { asm volatile("cp.async.wait_group 1;" ::: "memory"); }
        else           { asm volatile("cp.async.wait_group 0;" ::: "memory"); }
        __syncthreads();
        if (kn < 1024) {
            if (MODE == 1) stsA(nst);
            issue(nst, kn);
        }
        // compute on stage: 2 k16 steps
        #pragma unroll
        for (int s = 0; s < 2; s++) {
            const int kp = s*8;
            uint32_t a[2][4];
            #pragma unroll
            for (int i = 0; i < 2; i++) {
                int mb = wr*32 + i*16 + g;
                a[i][0] = SA[stage][mb    ][kp + tg];
                a[i][1] = SA[stage][mb + 8][kp + tg];
                a[i][2] = SA[stage][mb    ][kp + 4 + tg];
                a[i][3] = SA[stage][mb + 8][kp + 4 + tg];
            }
            uint32_t b[4][2];
            #pragma unroll
            for (int j = 0; j < 4; j++) {
                int nb = wc*32 + j*8 + g;
                b[j][0] = SB[stage][nb][kp + tg];
                b[j][1] = SB[stage][nb][kp + 4 + tg];
            }
            #pragma unroll
            for (int i = 0; i < 2; i++)
                #pragma unroll
                for (int j = 0; j < 4; j++)
                    mma_f16(acc[i][j], a[i][0], a[i][1], a[i][2], a[i][3],
                            b[j][0], b[j][1]);
        }
        __syncthreads();
    }

    // ---- epilogue ----
    #pragma unroll
    for (int i = 0; i < 2; i++) {
        #pragma unroll
        for (int j = 0; j < 4; j++) {
            int r0 = rowBase + wr*32 + i*16 + g;
            int c0 = colBase + wc*32 + j*8 + tg*2;
            #pragma unroll
            for (int e = 0; e < 4; e++) {
                int row = r0 + ((e >> 1) ? 8 : 0);
                int col = c0 + (e & 1);
                if (MODE == 0) {
                    float bias = (col < 3072) ? b1[col] : b2[col-3072];
                    g_XALL[(size_t)row*4096 + col] = acc[i][j][e] + bias;
                } else if (row < Mrows) {
                    Cout[(size_t)row*Nn + col] = acc[i][j][e];
                }
            }
        }
    }
}

// ---------------- legacy tf32 path for small attention/head GEMMs ----------------
__device__ __forceinline__ uint32_t f2tf32(float x){
    uint32_t r;
    asm("cvt.rna.tf32.f32 %0, %1;" : "=r"(r) : "f"(x));
    return r;
}
__device__ __forceinline__ void mma_tf32(float c[4],
    uint32_t a0, uint32_t a1, uint32_t a2, uint32_t a3,
    uint32_t b0, uint32_t b1)
{
    asm volatile(
        "mma.sync.aligned.m16n8k8.row.col.f32.tf32.tf32.f32 "
        "{%0,%1,%2,%3}, {%4,%5,%6,%7}, {%8,%9}, {%0,%1,%2,%3};"
        : "+f"(c[0]), "+f"(c[1]), "+f"(c[2]), "+f"(c[3])
        : "r"(a0), "r"(a1), "r"(a2), "r"(a3), "r"(b0), "r"(b1));
}
__device__ __forceinline__ void sts_row(uint32_t S[][20], int row, int k4, float4 v){
    uint4 t;
    t.x = f2tf32(v.x); t.y = f2tf32(v.y);
    t.z = f2tf32(v.z); t.w = f2tf32(v.w);
    *(uint4*)&S[row][k4] = t;
}
__device__ __forceinline__ void mma_tile16(float acc[2][4][4],
        const uint32_t As[][20], const uint32_t Bs[][20],
        int wr, int wc, int g, int tg)
{
    #pragma unroll
    for (int ks = 0; ks < 16; ks += 8) {
        uint32_t a[2][4];
        #pragma unroll
        for (int i = 0; i < 2; i++) {
            int mb = wr*32 + i*16 + g;
            a[i][0] = As[mb    ][ks + tg];
            a[i][1] = As[mb + 8][ks + tg];
            a[i][2] = As[mb    ][ks + 4 + tg];
            a[i][3] = As[mb + 8][ks + 4 + tg];
        }
        uint32_t b[4][2];
        #pragma unroll
        for (int j = 0; j < 4; j++) {
            int nb = wc*32 + j*8 + g;
            b[j][0] = Bs[nb][ks + tg];
            b[j][1] = Bs[nb][ks + 4 + tg];
        }
        #pragma unroll
        for (int i = 0; i < 2; i++)
            #pragma unroll
            for (int j = 0; j < 4; j++)
                mma_tf32(acc[i][j], a[i][0], a[i][1], a[i][2], a[i][3],
                         b[j][0], b[j][1]);
    }
}

template<bool BT, int ACT>
__global__ __launch_bounds__(128) void gemm_s(
    const float* __restrict__ A, const float* __restrict__ B,
    const float* __restrict__ bias, float* __restrict__ C,
    int M, int N, int K, int sA, int sB, int sC)
{
    A += (size_t)blockIdx.z * sA;
    B += (size_t)blockIdx.z * sB;
    C += (size_t)blockIdx.z * sC;

    __shared__ uint32_t As[2][64][20];
    __shared__ uint32_t Bs[2][64][20];
    const int tid  = threadIdx.x;
    const int lane = tid & 31, warp = tid >> 5;
    const int wr = warp >> 1, wc = warp & 1;
    const int g = lane >> 2, tg = lane & 3;
    const int rowBase = blockIdx.y*64, colBase = blockIdx.x*64;

    float4 rA[2], rB[2];
    auto loadA = [&](int k0){
        #pragma unroll
        for (int it = 0; it < 2; it++) {
            int idx = tid + it*128, row = idx >> 2, k4 = (idx & 3)*4;
            int gr = rowBase + row;
            rA[it] = (gr < M) ? *(const float4*)(A + (size_t)gr*K + k0 + k4)
                              : make_float4(0.f,0.f,0.f,0.f);
        }
    };
    auto loadB = [&](int k0){
        #pragma unroll
        for (int it = 0; it < 2; it++) {
            int idx = tid + it*128;
            if (BT) {
                int row = idx >> 2, k4 = (idx & 3)*4;
                int gn = colBase + row;
                rB[it] = (gn < N) ? *(const float4*)(B + (size_t)gn*K + k0 + k4)
                                  : make_float4(0.f,0.f,0.f,0.f);
            } else {
                int k = idx >> 4, n4 = (idx & 15)*4;
                rB[it] = *(const float4*)(B + (size_t)(k0+k)*N + colBase + n4);
            }
        }
    };
    auto stsAll = [&](int buf){
        #pragma unroll
        for (int it = 0; it < 2; it++) {
            int idx = tid + it*128;
            int rowA = idx >> 2, k4 = (idx & 3)*4;
            sts_row(As[buf], rowA, k4, rA[it]);
            if (BT) {
                sts_row(Bs[buf], rowA, k4, rB[it]);
            } else {
                int k = idx >> 4, n4 = (idx & 15)*4;
                Bs[buf][n4+0][k] = f2tf32(rB[it].x);
                Bs[buf][n4+1][k] = f2tf32(rB[it].y);
                Bs[buf][n4+2][k] = f2tf32(rB[it].z);
                Bs[buf][n4+3][k] = f2tf32(rB[it].w);
            }
        }
    };

    float acc[2][4][4];
    #pragma unroll
    for (int i=0;i<2;i++) for (int j=0;j<4;j++) for (int e=0;e<4;e++) acc[i][j][e]=0.f;

    loadA(0); loadB(0); stsAll(0); __syncthreads();
    int buf = 0;
    for (int k0 = 16; ; k0 += 16) {
        bool more = (k0 < K);
        if (more) { loadA(k0); loadB(k0); }
        mma_tile16(acc, As[buf], Bs[buf], wr, wc, g, tg);
        if (!more) break;
        buf ^= 1;
        stsAll(buf);
        __syncthreads();
    }

    #pragma unroll
    for (int i = 0; i < 2; i++) {
        #pragma unroll
        for (int j = 0; j < 4; j++) {
            int r0 = rowBase + wr*32 + i*16 + g;
            int c0 = colBase + wc*32 + j*8 + tg*2;
            #pragma unroll
            for (int e = 0; e < 4; e++) {
                int row = r0 + ((e >> 1) ? 8 : 0);
                int col = c0 + (e & 1);
                if (row < M && col < N) {
                    float v = acc[i][j][e];
                    if (bias) v += bias[col];
                    if (ACT == 1) v = tanhf(v);
                    else if (ACT == 2) v = fmaxf(v, 0.f);
                    C[(size_t)row*N + col] = v;
                }
            }
        }
    }
}

// ---------------- pointwise kernels ----------------
__global__ void k_embed(const int* __restrict__ lin, const int* __restrict__ rin,
                        const float* __restrict__ emb)
{
    int row = blockIdx.x;
    int t = row >> 9, n = row & 511;
    int tok = t ? rin[n] : lin[n];
    float4 v = ((const float4*)(emb + (size_t)tok*1024))[threadIdx.x];
    ((uint2*)(g_Xh + (size_t)row*1024))[threadIdx.x] = f4_to_h4(v);
}

__global__ void k_leaf(const float* __restrict__ b_iouh)
{
    int gid = blockIdx.x*256 + threadIdx.x;   // 2*256*1024
    int i = gid >> 10, m = gid & 1023;
    int t = i >> 8, j = i & 255;
    int r = d_S.leaf[j];
    size_t x = (size_t)(t*512 + r);
    float ig = g_XALL[x*4096 + m]        + b_iouh[m];
    float og = g_XALL[x*4096 + 1024 + m] + b_iouh[1024 + m];
    float ug = g_XALL[x*4096 + 2048 + m] + b_iouh[2048 + m];
    float c = sigm(ig) * tanhf(ug);
    float hv = sigm(og) * tanhf(c);
    g_C[x*1024 + m] = c;
    g_H[x*1024 + m] = hv;
    g_Hh[x*1024 + m] = __float2half(hv);
}

__global__ void k_point(const int* __restrict__ cidx, const float* __restrict__ cmask,
                        int h, int Bn,
                        const float* __restrict__ b_iouh, const float* __restrict__ b_fh)
{
    int gid = blockIdx.x*256 + threadIdx.x;
    if (gid >= 2*Bn*1024) return;
    int i = gid >> 10, m = gid & 1023;
    int t = i >= Bn; int j = i - (t ? Bn : 0);
    int r = d_S.lvl[h][j];
    size_t x = (size_t)(t*512 + r);
    float ig = g_XALL[x*4096 + m]        + g_IOU[(size_t)i*3072 + m]        + b_iouh[m];
    float og = g_XALL[x*4096 + 1024 + m] + g_IOU[(size_t)i*3072 + 1024 + m] + b_iouh[1024 + m];
    float ug = g_XALL[x*4096 + 2048 + m] + g_IOU[(size_t)i*3072 + 2048 + m] + b_iouh[2048 + m];
    float xf = g_XALL[x*4096 + 3072 + m];
    float f0 = sigm(g_FP[(size_t)(2*i  )*1024 + m] + b_fh[m] + xf);
    float f1 = sigm(g_FP[(size_t)(2*i+1)*1024 + m] + b_fh[m] + xf);
    int c0 = cidx[2*r], c1 = cidx[2*r+1];
    float m0 = cmask[2*r], m1 = cmask[2*r+1];
    float cc0 = g_C[((size_t)(t*512 + c0))*1024 + m] * m0;
    float cc1 = g_C[((size_t)(t*512 + c1))*1024 + m] * m1;
    float c = sigm(ig)*tanhf(ug) + f0*cc0 + f1*cc1;
    float hv = sigm(og)*tanhf(c);
    g_C[x*1024 + m] = c;
    g_H[x*1024 + m] = hv;
    g_Hh[x*1024 + m] = __float2half(hv);
}

__global__ void k_soft(float* __restrict__ out)
{
    __shared__ float sh[512];
    int b = blockIdx.x;                 // t*16 + hop
    int t = b >> 4, hop = b & 15;
    int n = threadIdx.x;
    float v = g_LOG[(size_t)(t*512 + n)*16 + hop];
    sh[n] = v; __syncthreads();
    for (int s=256; s>0; s>>=1){ if (n < s) sh[n] = fmaxf(sh[n], sh[n+s]); __syncthreads(); }
    float mx = sh[0]; __syncthreads();
    float e = expf(v - mx);
    sh[n] = e; __syncthreads();
    for (int s=256; s>0; s>>=1){ if (n < s) sh[n] += sh[n+s]; __syncthreads(); }
    float a = e / sh[0];
    g_ALPHA[(size_t)b*512 + n] = a;
    out[5 + t*8192 + hop*512 + n] = a;
}

__global__ void k_lat(const float* __restrict__ w_lat, const float* __restrict__ b_lat)
{
    int m = blockIdx.x*256 + threadIdx.x;
    float lv = b_lat[0], rv = b_lat[0];
    #pragma unroll
    for (int h=0; h<16; h++) {
        float w = w_lat[h];
        lv += w * g_LS[h*1024 + m];
        rv += w * g_LS[(16 + h)*1024 + m];
    }
    g_FR[m]        = fabsf(lv - rv);
    g_FR[1024 + m] = lv * rv;
    g_FR[2048 + m] = 0.5f * (lv + rv);
}

__global__ void k_fc(const float* __restrict__ w, const float* __restrict__ bb)
{
    int o = blockIdx.x*8 + (threadIdx.x >> 5);
    int lane = threadIdx.x & 31;
    const float* wr = w + (size_t)o*3072;
    float s = 0.f;
    for (int k=lane; k<3072; k+=32) s += g_FR[k]*wr[k];
    for (int d=16; d; d>>=1) s += __shfl_down_sync(0xffffffffu, s, d);
    if (!lane) { float v = s + bb[o]; g_FC[o] = v > 0.f ? v : 0.01f*v; }
}

__global__ void k_fc2out(const float* __restrict__ w_out, const float* __restrict__ b_out,
                         const float* __restrict__ w_out1, const float* __restrict__ b_out1,
                         float* __restrict__ out)
{
    __shared__ float fc2[256];
    __shared__ float logit[5];
    int tid = threadIdx.x;             // 256
    int wid = tid >> 5, lane = tid & 31;
    for (int it = 0; it < 4; it++) {
        int o = wid*32 + (it << 3) + (lane >> 2);
        float s = 0.f;
        for (int k = (lane & 3); k < 512; k += 4) s += g_FC[k]*w_out[(size_t)o*512 + k];
        s += __shfl_down_sync(0xffffffffu, s, 2);
        s += __shfl_down_sync(0xffffffffu, s, 1);
        if ((lane & 3) == 0) fc2[o] = sigm(s + b_out[o]);
    }
    __syncthreads();
    if (wid < 5) {
        float s = 0.f;
        for (int k = lane; k < 256; k += 32) s += fc2[k]*w_out1[wid*256 + k];
        for (int d = 16; d; d >>= 1) s += __shfl_down_sync(0xffffffffu, s, d);
        if (!lane) logit[wid] = s + b_out1[wid];
    }
    __syncthreads();
    if (tid == 0) {
        float mx = logit[0];
        for (int c=1;c<5;c++) mx = fmaxf(mx, logit[c]);
        float sum = 0.f;
        for (int c=0;c<5;c++) sum += expf(logit[c]-mx);
        float l = logf(sum);
        for (int c=0;c<5;c++) out[c] = logit[c] - mx - l;
    }
}

// ---------------- launch ----------------
extern "C" void kernel_launch(void* const* d_in, const int* in_sizes, int n_in,
                              void* d_out, int out_size)
{
    const int*   linputs    = (const int*)  d_in[0];
    const int*   rinputs    = (const int*)  d_in[1];
    const int*   child_idx  = (const int*)  d_in[2];
    const float* child_mask = (const float*)d_in[3];
    const float* emb        = (const float*)d_in[4];
    const float* w_ioux     = (const float*)d_in[5];
    const float* b_ioux     = (const float*)d_in[6];
    const float* w_iouh     = (const float*)d_in[7];
    const float* b_iouh     = (const float*)d_in[8];
    const float* w_fx       = (const float*)d_in[9];
    const float* b_fx       = (const float*)d_in[10];
    const float* w_fh       = (const float*)d_in[11];
    const float* b_fh       = (const float*)d_in[12];
    const float* ws1        = (const float*)d_in[13];
    const float* ws2        = (const float*)d_in[14];
    const float* wf         = (const float*)d_in[15];
    const float* w_lat      = (const float*)d_in[16];
    const float* b_lat      = (const float*)d_in[17];
    const float* w_fc       = (const float*)d_in[18];
    const float* b_fc       = (const float*)d_in[19];
    const float* w_out      = (const float*)d_in[20];
    const float* b_out      = (const float*)d_in[21];
    const float* w_out1     = (const float*)d_in[22];
    const float* b_out1     = (const float*)d_in[23];
    float* out = (float*)d_out;

    float *pH, *pHB, *pLOG, *pALPHA, *pM, *pLS;
    cudaGetSymbolAddress((void**)&pH,     g_H);
    cudaGetSymbolAddress((void**)&pHB,    g_HB);
    cudaGetSymbolAddress((void**)&pLOG,   g_LOG);
    cudaGetSymbolAddress((void**)&pALPHA, g_ALPHA);
    cudaGetSymbolAddress((void**)&pM,     g_Mm);
    cudaGetSymbolAddress((void**)&pLS,    g_LS);

    // 0) weight conversion to half (independent of embed)
    k_cvtW<<<8192, 256>>>(w_ioux, w_fx, w_iouh, w_fh);

    // 1) embedding gather (half)
    k_embed<<<1024, 256>>>(linputs, rinputs, emb);

    // 2) fused input projections: M=1024, N=4096, K=1024
    gemm_h<0><<<dim3(64, 8, 1), 256>>>(b_ioux, b_fx, nullptr, nullptr, 0, 0);

    // 3) leaves
    k_leaf<<<2048, 256>>>(b_iouh);

    // 4) internal levels
    for (int h = 1; h <= 15; h++) {
        int B = SCHED.cnt[h];
        if (B == 0) continue;
        int ny = (4*B + 127)/128; if (ny < 1) ny = 1;
        gemm_h<1><<<dim3(48, ny, 2), 256>>>(nullptr, nullptr,
                                            child_idx, child_mask, h, B);
        k_point<<<(2*B*1024 + 255)/256, 256>>>(child_idx, child_mask, h, B, b_iouh, b_fh);
    }

    // 5) attention (tf32)
    gemm_s<true,1><<<dim3(4,16,1), 128>>>(pH, ws1, nullptr, pHB,
                                          1024, 256, 1024, 0, 0, 0);
    gemm_s<true,0><<<dim3(1,16,1), 128>>>(pHB, ws2, nullptr, pLOG,
                                          1024, 16, 256, 0, 0, 0);
    k_soft<<<32, 512>>>(out);
    gemm_s<false,0><<<dim3(16,1,2), 128>>>(pALPHA, pH, nullptr, pM,
                                           16, 1024, 512, 16*512, 512*1024, 16*1024);

    // 6) head
    gemm_s<false,2><<<dim3(16,1,1), 128>>>(pM, wf, nullptr, pLS,
                                           32, 1024, 1024, 0, 0, 0);
    k_lat<<<4, 256>>>(w_lat, b_lat);
    k_fc<<<64, 256>>>(w_fc, b_fc);
    k_fc2out<<<1, 256>>>(w_out, b_out, w_out1, b_out1, out);
}

// round 12
// speedup vs baseline: 4.1477x; 1.3080x over previous
#include <cuda_runtime.h>
#include <cuda_fp16.h>
#include <math.h>
#include <stdint.h>

// ---------------- static device scratch ----------------
__device__ __align__(16) float g_XALL[2*512*4096];   // [iou(3072) | f(1024)] per row
__device__ __align__(16) float g_H[2*512*1024];
__device__ __align__(16) float g_C[2*512*1024];
__device__ __align__(16) float g_IOU[2*256*3072];    // two split-K partials
__device__ __align__(16) float g_FP[2*512*1024];     // two split-K partials
__device__ __align__(16) float g_HB[1024*256];
__device__ __align__(16) float g_LOG[1024*16];
__device__ __align__(16) float g_ALPHA[2*16*512];
__device__ __align__(16) float g_Mm[32*1024];
__device__ __align__(16) float g_LS[32*1024];
__device__ __align__(16) float g_FR[3072];
__device__ __align__(16) float g_FC[512];
// half-precision operand copies
__device__ __align__(16) __half g_Wx[4096*1024];     // [w_ioux rows | w_fx rows]
__device__ __align__(16) __half g_Wiouh[3072*1024];
__device__ __align__(16) __half g_Wfh[1024*1024];
__device__ __align__(16) __half g_Ws1h[256*1024];
__device__ __align__(16) __half g_Xh[1024*1024];
__device__ __align__(16) __half g_Hh[2*512*1024];

// ---------------- compile-time tree schedule (N=512 heap, DFS post-order) ----------------
struct Sched {
    int leaf[256];
    int cnt[16];
    int lvl[16][128];
};

constexpr Sched make_sched() {
    Sched s{};
    int order[512] = {}; int rankOf[512] = {}; int height[512] = {};
    int stN[64] = {}; int stP[64] = {};
    int sp = 1, cnt = 0;
    stN[0] = 0; stP[0] = 0;
    while (sp) {
        int j = stN[sp-1], p = stP[sp-1];
        if (p < 2) {
            stP[sp-1] = p + 1;
            int c = 2*j + 1 + p;
            if (c < 512) { stN[sp] = c; stP[sp] = 0; sp++; }
        } else { order[cnt] = j; rankOf[j] = cnt; cnt++; sp--; }
    }
    int nleaf = 0;
    for (int r = 0; r < 512; r++) {
        int j = order[r]; int h = 0;
        for (int k = 0; k < 2; k++) {
            int c = 2*j + 1 + k;
            if (c < 512) { int hh = height[rankOf[c]] + 1; if (hh > h) h = hh; }
        }
        height[r] = h;
        if (h == 0) s.leaf[nleaf++] = r;
        else        s.lvl[h][s.cnt[h]++] = r;
    }
    return s;
}

constexpr Sched SCHED = make_sched();
__device__ const Sched d_S = make_sched();

__device__ __forceinline__ float sigm(float x){ return 1.f/(1.f+expf(-x)); }

__device__ __forceinline__ uint2 f4_to_h4(float4 v){
    __half2 p0 = __floats2half2_rn(v.x, v.y);
    __half2 p1 = __floats2half2_rn(v.z, v.w);
    uint2 r; r.x = *(uint32_t*)&p0; r.y = *(uint32_t*)&p1;
    return r;
}

__device__ __forceinline__ uint32_t smem_u32(const void* p){
    uint32_t a;
    asm("{ .reg .u64 t; cvta.to.shared.u64 t, %1; cvt.u32.u64 %0, t; }" : "=r"(a) : "l"(p));
    return a;
}
__device__ __forceinline__ void cpa16(uint32_t dst, const void* src){
    asm volatile("cp.async.cg.shared.global [%0], [%1], 16;" :: "r"(dst), "l"(src));
}

__device__ __forceinline__ void mma_f16(float c[4],
    uint32_t a0, uint32_t a1, uint32_t a2, uint32_t a3,
    uint32_t b0, uint32_t b1)
{
    asm volatile(
        "mma.sync.aligned.m16n8k16.row.col.f32.f16.f16.f32 "
        "{%0,%1,%2,%3}, {%4,%5,%6,%7}, {%8,%9}, {%0,%1,%2,%3};"
        : "+f"(c[0]), "+f"(c[1]), "+f"(c[2]), "+f"(c[3])
        : "r"(a0), "r"(a1), "r"(a2), "r"(a3), "r"(b0), "r"(b1));
}

// ---------------- weight pre-conversion (fp32 -> half), flat ----------------
// totals (float4 groups): w_ioux 786432 | w_fx 262144 | w_iouh 786432 | w_fh 262144 | ws1 65536
// cumulative:            786432 / 1048576 / 1835008 / 2097152 / 2162688
__global__ void k_cvtW(const float* __restrict__ w_ioux, const float* __restrict__ w_fx,
                       const float* __restrict__ w_iouh, const float* __restrict__ w_fh,
                       const float* __restrict__ ws1)
{
    int i = blockIdx.x*256 + threadIdx.x;
    if (i >= 2162688) return;
    const float4* src; uint2* dst;
    if (i < 786432)       { src = (const float4*)w_ioux + i;            dst = (uint2*)g_Wx + i; }
    else if (i < 1048576) { int j = i -  786432; src = (const float4*)w_fx   + j; dst = (uint2*)g_Wx + 786432 + j; }
    else if (i < 1835008) { int j = i - 1048576; src = (const float4*)w_iouh + j; dst = (uint2*)g_Wiouh + j; }
    else if (i < 2097152) { int j = i - 1835008; src = (const float4*)w_fh   + j; dst = (uint2*)g_Wfh + j; }
    else                  { int j = i - 2097152; src = (const float4*)ws1    + j; dst = (uint2*)g_Ws1h + j; }
    *dst = f4_to_h4(*src);
}

// ---------------- fp16 cp.async-pipelined GEMM, 128x64 tile, k-chunk 32, 3 stages ----
// MODE 0: A = g_Xh (M=1024), B = g_Wx (N=4096), C = g_XALL + split bias
// MODE 1: per-level, split-K=2; blockIdx.z = which*2 + khalf:
//         which=0: A row = masked child-H sum  (M=2Bn), B=g_Wiouh (N=3072), C=g_IOU[khalf]
//         which=1: A row = single masked child (M=4Bn), B=g_Wfh   (N=1024), C=g_FP[khalf]
// MODE 2: A = g_Hh (M=1024), B = g_Ws1h (N=256), C = tanh -> g_HB
template<int MODE>
__global__ __launch_bounds__(256)
void gemm_h(const float* __restrict__ b1, const float* __restrict__ b2,
            const int* __restrict__ cidx, const float* __restrict__ cmask,
            int h, int Bn)
{
    constexpr int NCH = (MODE == 1) ? 16 : 32;   // k-chunks of 32
    constexpr int KTOT = NCH * 32;
    int Mrows, Nn, zwhich = 0, kbase = 0;
    const __half* Aw = nullptr;
    const __half* Bw;
    float* Cout;
    if (MODE == 0) {
        Mrows = 1024; Nn = 4096; Bw = g_Wx; Cout = g_XALL; Aw = g_Xh;
    } else if (MODE == 2) {
        Mrows = 1024; Nn = 256; Bw = g_Ws1h; Cout = g_HB; Aw = g_Hh;
    } else {
        int z = blockIdx.z;
        zwhich = z >> 1; int khalf = z & 1;
        Mrows = zwhich ? 4*Bn : 2*Bn;
        Nn    = zwhich ? 1024 : 3072;
        Bw    = zwhich ? g_Wfh : g_Wiouh;
        Cout  = zwhich ? (g_FP + khalf*512*1024) : (g_IOU + khalf*256*3072);
        kbase = khalf * 512;
    }
    const int rowBase = blockIdx.y * 128;
    const int colBase = blockIdx.x * 64;
    if (rowBase >= Mrows || colBase >= Nn) return;

    __shared__ uint32_t SA[3][128][20];
    __shared__ uint32_t SB[3][64][20];

    const int tid  = threadIdx.x;
    const int lane = tid & 31, warp = tid >> 5;
    const int wr = warp >> 1;            // 0..3
    const int wc = warp & 1;             // 0..1
    const int g  = lane >> 2, tg = lane & 3;

    const uint32_t baA = smem_u32(&SA[0][0][0]);
    const uint32_t baB = smem_u32(&SB[0][0][0]);

    // ---- per-thread gather setup (MODE 1 A rows; fixed across k) ----
    const __half* aptr0[2]; const __half* aptr1[2];
    __half2 am0[2], am1[2]; bool avalid[2]; int arow[2], ach[2];
    #pragma unroll
    for (int it = 0; it < 2; it++) {
        int idx = tid + (it << 8);
        int row = idx >> 2, ch = idx & 3;
        arow[it] = row; ach[it] = ch;
        int gr = rowBase + row;
        avalid[it] = false;
        if (MODE == 1 && gr < Mrows) {
            avalid[it] = true;
            if (zwhich == 0) {
                int t = gr >= Bn; int j = gr - (t ? Bn : 0);
                int r = d_S.lvl[h][j];
                aptr0[it] = g_Hh + ((size_t)(t*512 + cidx[2*r  ]))*1024 + ch*8;
                aptr1[it] = g_Hh + ((size_t)(t*512 + cidx[2*r+1]))*1024 + ch*8;
                am0[it] = __float2half2_rn(cmask[2*r]);
                am1[it] = __float2half2_rn(cmask[2*r+1]);
            } else {
                int t = gr >= 2*Bn; int rem = gr - (t ? 2*Bn : 0);
                int j = rem >> 1, ck = rem & 1;
                int r = d_S.lvl[h][j];
                aptr0[it] = g_Hh + ((size_t)(t*512 + cidx[2*r+ck]))*1024 + ch*8;
                aptr1[it] = aptr0[it];
                am0[it] = __float2half2_rn(cmask[2*r+ck]);
                am1[it] = __float2half2_rn(0.f);
            }
        }
    }

    // ---- zero-fill invalid A rows in all stages (persist across rotation) ----
    if (MODE == 1) {
        const uint4 zz = make_uint4(0,0,0,0);
        #pragma unroll
        for (int s = 0; s < 3; s++)
            #pragma unroll
            for (int it = 0; it < 2; it++)
                if (!avalid[it]) *(uint4*)&SA[s][arow[it]][ach[it]*4] = zz;
    }

    auto issue = [&](int stage, int k0){
        { // B: 64 rows x 4 chunks = 256 -> 1 per thread
            int row = tid >> 2, ch = tid & 3;
            cpa16(baB + ((stage*64 + row)*20 + ch*4)*4,
                  Bw + (size_t)(colBase + row)*1024 + k0 + ch*8);
        }
        if (MODE != 1) {
            #pragma unroll
            for (int it = 0; it < 2; it++) {
                int idx = tid + (it << 8);
                int row = idx >> 2, ch = idx & 3;
                cpa16(baA + ((stage*128 + row)*20 + ch*4)*4,
                      Aw + (size_t)(rowBase + row)*1024 + k0 + ch*8);
            }
        }
        asm volatile("cp.async.commit_group;" ::: "memory");
    };

    float acc[2][4][4];
    #pragma unroll
    for (int i=0;i<2;i++) for (int j=0;j<4;j++) for (int e=0;e<4;e++) acc[i][j][e]=0.f;

    // MODE 1: manual A gather
    uint4 va[2];
    auto gatherA = [&](int k0){
        #pragma unroll
        for (int it = 0; it < 2; it++) {
            if (!avalid[it]) continue;
            uint4 u0 = *(const uint4*)(aptr0[it] + k0);
            uint4 u1 = *(const uint4*)(aptr1[it] + k0);
            __half2* a = (__half2*)&u0; __half2* b = (__half2*)&u1;
            uint4 r;
            __half2* o = (__half2*)&r;
            #pragma unroll
            for (int w = 0; w < 4; w++)
                o[w] = (zwhich==0) ? __hfma2(b[w], am1[it], __hmul2(a[w], am0[it]))
                                   : __hmul2(a[w], am0[it]);
            va[it] = r;
        }
    };
    auto stsA = [&](int stage){
        #pragma unroll
        for (int it = 0; it < 2; it++)
            if (avalid[it]) *(uint4*)&SA[stage][arow[it]][ach[it]*4] = va[it];
    };

    if (MODE == 1) { gatherA(kbase);      stsA(0); }
    issue(0, kbase);
    if (MODE == 1) { gatherA(kbase + 32); stsA(1); }
    issue(1, kbase + 32);

    for (int c = 0; c < NCH; c++) {
        const int stage = c % 3;
        const int kn = (c + 2) * 32;
        const int nst = (c + 2) % 3;
        if (MODE == 1 && kn < KTOT) gatherA(kbase + kn);
        if (kn < KTOT) { asm volatile("cp.async.wait_group 1;" ::: "memory"); }
        else           { asm volatile("cp.async.wait_group 0;" ::: "memory"); }
        __syncthreads();
        if (kn < KTOT) {
            if (MODE == 1) stsA(nst);
            issue(nst, kbase + kn);
        }
        // compute on stage: 2 k16 steps
        #pragma unroll
        for (int s = 0; s < 2; s++) {
            const int kp = s*8;
            uint32_t a[2][4];
            #pragma unroll
            for (int i = 0; i < 2; i++) {
                int mb = wr*32 + i*16 + g;
                a[i][0] = SA[stage][mb    ][kp + tg];
                a[i][1] = SA[stage][mb + 8][kp + tg];
                a[i][2] = SA[stage][mb    ][kp + 4 + tg];
                a[i][3] = SA[stage][mb + 8][kp + 4 + tg];
            }
            uint32_t b[4][2];
            #pragma unroll
            for (int j = 0; j < 4; j++) {
                int nb = wc*32 + j*8 + g;
                b[j][0] = SB[stage][nb][kp + tg];
                b[j][1] = SB[stage][nb][kp + 4 + tg];
            }
            #pragma unroll
            for (int i = 0; i < 2; i++)
                #pragma unroll
                for (int j = 0; j < 4; j++)
                    mma_f16(acc[i][j], a[i][0], a[i][1], a[i][2], a[i][3],
                            b[j][0], b[j][1]);
        }
        __syncthreads();
    }

    // ---- epilogue ----
    #pragma unroll
    for (int i = 0; i < 2; i++) {
        #pragma unroll
        for (int j = 0; j < 4; j++) {
            int r0 = rowBase + wr*32 + i*16 + g;
            int c0 = colBase + wc*32 + j*8 + tg*2;
            #pragma unroll
            for (int e = 0; e < 4; e++) {
                int row = r0 + ((e >> 1) ? 8 : 0);
                int col = c0 + (e & 1);
                if (MODE == 0) {
                    float bias = (col < 3072) ? b1[col] : b2[col-3072];
                    g_XALL[(size_t)row*4096 + col] = acc[i][j][e] + bias;
                } else if (MODE == 2) {
                    g_HB[(size_t)row*256 + col] = tanhf(acc[i][j][e]);
                } else if (row < Mrows) {
                    Cout[(size_t)row*Nn + col] = acc[i][j][e];
                }
            }
        }
    }
}

// ---------------- legacy tf32 path for small attention/head GEMMs ----------------
__device__ __forceinline__ uint32_t f2tf32(float x){
    uint32_t r;
    asm("cvt.rna.tf32.f32 %0, %1;" : "=r"(r) : "f"(x));
    return r;
}
__device__ __forceinline__ void mma_tf32(float c[4],
    uint32_t a0, uint32_t a1, uint32_t a2, uint32_t a3,
    uint32_t b0, uint32_t b1)
{
    asm volatile(
        "mma.sync.aligned.m16n8k8.row.col.f32.tf32.tf32.f32 "
        "{%0,%1,%2,%3}, {%4,%5,%6,%7}, {%8,%9}, {%0,%1,%2,%3};"
        : "+f"(c[0]), "+f"(c[1]), "+f"(c[2]), "+f"(c[3])
        : "r"(a0), "r"(a1), "r"(a2), "r"(a3), "r"(b0), "r"(b1));
}
__device__ __forceinline__ void sts_row(uint32_t S[][20], int row, int k4, float4 v){
    uint4 t;
    t.x = f2tf32(v.x); t.y = f2tf32(v.y);
    t.z = f2tf32(v.z); t.w = f2tf32(v.w);
    *(uint4*)&S[row][k4] = t;
}
__device__ __forceinline__ void mma_tile16(float acc[2][4][4],
        const uint32_t As[][20], const uint32_t Bs[][20],
        int wr, int wc, int g, int tg)
{
    #pragma unroll
    for (int ks = 0; ks < 16; ks += 8) {
        uint32_t a[2][4];
        #pragma unroll
        for (int i = 0; i < 2; i++) {
            int mb = wr*32 + i*16 + g;
            a[i][0] = As[mb    ][ks + tg];
            a[i][1] = As[mb + 8][ks + tg];
            a[i][2] = As[mb    ][ks + 4 + tg];
            a[i][3] = As[mb + 8][ks + 4 + tg];
        }
        uint32_t b[4][2];
        #pragma unroll
        for (int j = 0; j < 4; j++) {
            int nb = wc*32 + j*8 + g;
            b[j][0] = Bs[nb][ks + tg];
            b[j][1] = Bs[nb][ks + 4 + tg];
        }
        #pragma unroll
        for (int i = 0; i < 2; i++)
            #pragma unroll
            for (int j = 0; j < 4; j++)
                mma_tf32(acc[i][j], a[i][0], a[i][1], a[i][2], a[i][3],
                         b[j][0], b[j][1]);
    }
}

template<bool BT, int ACT>
__global__ __launch_bounds__(128) void gemm_s(
    const float* __restrict__ A, const float* __restrict__ B,
    const float* __restrict__ bias, float* __restrict__ C,
    int M, int N, int K, int sA, int sB, int sC)
{
    A += (size_t)blockIdx.z * sA;
    B += (size_t)blockIdx.z * sB;
    C += (size_t)blockIdx.z * sC;

    __shared__ uint32_t As[2][64][20];
    __shared__ uint32_t Bs[2][64][20];
    const int tid  = threadIdx.x;
    const int lane = tid & 31, warp = tid >> 5;
    const int wr = warp >> 1, wc = warp & 1;
    const int g = lane >> 2, tg = lane & 3;
    const int rowBase = blockIdx.y*64, colBase = blockIdx.x*64;

    float4 rA[2], rB[2];
    auto loadA = [&](int k0){
        #pragma unroll
        for (int it = 0; it < 2; it++) {
            int idx = tid + it*128, row = idx >> 2, k4 = (idx & 3)*4;
            int gr = rowBase + row;
            rA[it] = (gr < M) ? *(const float4*)(A + (size_t)gr*K + k0 + k4)
                              : make_float4(0.f,0.f,0.f,0.f);
        }
    };
    auto loadB = [&](int k0){
        #pragma unroll
        for (int it = 0; it < 2; it++) {
            int idx = tid + it*128;
            if (BT) {
                int row = idx >> 2, k4 = (idx & 3)*4;
                int gn = colBase + row;
                rB[it] = (gn < N) ? *(const float4*)(B + (size_t)gn*K + k0 + k4)
                                  : make_float4(0.f,0.f,0.f,0.f);
            } else {
                int k = idx >> 4, n4 = (idx & 15)*4;
                rB[it] = *(const float4*)(B + (size_t)(k0+k)*N + colBase + n4);
            }
        }
    };
    auto stsAll = [&](int buf){
        #pragma unroll
        for (int it = 0; it < 2; it++) {
            int idx = tid + it*128;
            int rowA = idx >> 2, k4 = (idx & 3)*4;
            sts_row(As[buf], rowA, k4, rA[it]);
            if (BT) {
                sts_row(Bs[buf], rowA, k4, rB[it]);
            } else {
                int k = idx >> 4, n4 = (idx & 15)*4;
                Bs[buf][n4+0][k] = f2tf32(rB[it].x);
                Bs[buf][n4+1][k] = f2tf32(rB[it].y);
                Bs[buf][n4+2][k] = f2tf32(rB[it].z);
                Bs[buf][n4+3][k] = f2tf32(rB[it].w);
            }
        }
    };

    float acc[2][4][4];
    #pragma unroll
    for (int i=0;i<2;i++) for (int j=0;j<4;j++) for (int e=0;e<4;e++) acc[i][j][e]=0.f;

    loadA(0); loadB(0); stsAll(0); __syncthreads();
    int buf = 0;
    for (int k0 = 16; ; k0 += 16) {
        bool more = (k0 < K);
        if (more) { loadA(k0); loadB(k0); }
        mma_tile16(acc, As[buf], Bs[buf], wr, wc, g, tg);
        if (!more) break;
        buf ^= 1;
        stsAll(buf);
        __syncthreads();
    }

    #pragma unroll
    for (int i = 0; i < 2; i++) {
        #pragma unroll
        for (int j = 0; j < 4; j++) {
            int r0 = rowBase + wr*32 + i*16 + g;
            int c0 = colBase + wc*32 + j*8 + tg*2;
            #pragma unroll
            for (int e = 0; e < 4; e++) {
                int row = r0 + ((e >> 1) ? 8 : 0);
                int col = c0 + (e & 1);
                if (row < M && col < N) {
                    float v = acc[i][j][e];
                    if (bias) v += bias[col];
                    if (ACT == 1) v = tanhf(v);
                    else if (ACT == 2) v = fmaxf(v, 0.f);
                    C[(size_t)row*N + col] = v;
                }
            }
        }
    }
}

// ---------------- pointwise kernels ----------------
__global__ void k_embed(const int* __restrict__ lin, const int* __restrict__ rin,
                        const float* __restrict__ emb)
{
    int row = blockIdx.x;
    int t = row >> 9, n = row & 511;
    int tok = t ? rin[n] : lin[n];
    float4 v = ((const float4*)(emb + (size_t)tok*1024))[threadIdx.x];
    ((uint2*)(g_Xh + (size_t)row*1024))[threadIdx.x] = f4_to_h4(v);
}

__global__ void k_leaf(const float* __restrict__ b_iouh)
{
    int gid = blockIdx.x*256 + threadIdx.x;   // 2*256*1024
    int i = gid >> 10, m = gid & 1023;
    int t = i >> 8, j = i & 255;
    int r = d_S.leaf[j];
    size_t x = (size_t)(t*512 + r);
    float ig = g_XALL[x*4096 + m]        + b_iouh[m];
    float og = g_XALL[x*4096 + 1024 + m] + b_iouh[1024 + m];
    float ug = g_XALL[x*4096 + 2048 + m] + b_iouh[2048 + m];
    float c = sigm(ig) * tanhf(ug);
    float hv = sigm(og) * tanhf(c);
    g_C[x*1024 + m] = c;
    g_H[x*1024 + m] = hv;
    g_Hh[x*1024 + m] = __float2half(hv);
}

__global__ void k_point(const int* __restrict__ cidx, const float* __restrict__ cmask,
                        int h, int Bn,
                        const float* __restrict__ b_iouh, const float* __restrict__ b_fh)
{
    int gid = blockIdx.x*256 + threadIdx.x;
    if (gid >= 2*Bn*1024) return;
    int i = gid >> 10, m = gid & 1023;
    int t = i >= Bn; int j = i - (t ? Bn : 0);
    int r = d_S.lvl[h][j];
    size_t x = (size_t)(t*512 + r);
    const size_t IOFF = (size_t)256*3072;
    const size_t FOFF = (size_t)512*1024;
    float iou0 = g_IOU[(size_t)i*3072 + m]        + g_IOU[IOFF + (size_t)i*3072 + m];
    float iou1 = g_IOU[(size_t)i*3072 + 1024 + m] + g_IOU[IOFF + (size_t)i*3072 + 1024 + m];
    float iou2 = g_IOU[(size_t)i*3072 + 2048 + m] + g_IOU[IOFF + (size_t)i*3072 + 2048 + m];
    float ig = g_XALL[x*4096 + m]        + iou0 + b_iouh[m];
    float og = g_XALL[x*4096 + 1024 + m] + iou1 + b_iouh[1024 + m];
    float ug = g_XALL[x*4096 + 2048 + m] + iou2 + b_iouh[2048 + m];
    float xf = g_XALL[x*4096 + 3072 + m];
    float fp0 = g_FP[(size_t)(2*i  )*1024 + m] + g_FP[FOFF + (size_t)(2*i  )*1024 + m];
    float fp1 = g_FP[(size_t)(2*i+1)*1024 + m] + g_FP[FOFF + (size_t)(2*i+1)*1024 + m];
    float f0 = sigm(fp0 + b_fh[m] + xf);
    float f1 = sigm(fp1 + b_fh[m] + xf);
    int c0 = cidx[2*r], c1 = cidx[2*r+1];
    float m0 = cmask[2*r], m1 = cmask[2*r+1];
    float cc0 = g_C[((size_t)(t*512 + c0))*1024 + m] * m0;
    float cc1 = g_C[((size_t)(t*512 + c1))*1024 + m] * m1;
    float c = sigm(ig)*tanhf(ug) + f0*cc0 + f1*cc1;
    float hv = sigm(og)*tanhf(c);
    g_C[x*1024 + m] = c;
    g_H[x*1024 + m] = hv;
    g_Hh[x*1024 + m] = __float2half(hv);
}

__global__ void k_soft(float* __restrict__ out)
{
    __shared__ float sh[512];
    int b = blockIdx.x;                 // t*16 + hop
    int t = b >> 4, hop = b & 15;
    int n = threadIdx.x;
    float v = g_LOG[(size_t)(t*512 + n)*16 + hop];
    sh[n] = v; __syncthreads();
    for (int s=256; s>0; s>>=1){ if (n < s) sh[n] = fmaxf(sh[n], sh[n+s]); __syncthreads(); }
    float mx = sh[0]; __syncthreads();
    float e = expf(v - mx);
    sh[n] = e; __syncthreads();
    for (int s=256; s>0; s>>=1){ if (n < s) sh[n] += sh[n+s]; __syncthreads(); }
    float a = e / sh[0];
    g_ALPHA[(size_t)b*512 + n] = a;
    out[5 + t*8192 + hop*512 + n] = a;
}

__global__ void k_lat(const float* __restrict__ w_lat, const float* __restrict__ b_lat)
{
    int m = blockIdx.x*256 + threadIdx.x;
    float lv = b_lat[0], rv = b_lat[0];
    #pragma unroll
    for (int h=0; h<16; h++) {
        float w = w_lat[h];
        lv += w * g_LS[h*1024 + m];
        rv += w * g_LS[(16 + h)*1024 + m];
    }
    g_FR[m]        = fabsf(lv - rv);
    g_FR[1024 + m] = lv * rv;
    g_FR[2048 + m] = 0.5f * (lv + rv);
}

__global__ void k_fc(const float* __restrict__ w, const float* __restrict__ bb)
{
    int o = blockIdx.x*8 + (threadIdx.x >> 5);
    int lane = threadIdx.x & 31;
    const float* wr = w + (size_t)o*3072;
    float s = 0.f;
    for (int k=lane; k<3072; k+=32) s += g_FR[k]*wr[k];
    for (int d=16; d; d>>=1) s += __shfl_down_sync(0xffffffffu, s, d);
    if (!lane) { float v = s + bb[o]; g_FC[o] = v > 0.f ? v : 0.01f*v; }
}

__global__ void k_fc2out(const float* __restrict__ w_out, const float* __restrict__ b_out,
                         const float* __restrict__ w_out1, const float* __restrict__ b_out1,
                         float* __restrict__ out)
{
    __shared__ float fc2[256];
    __shared__ float logit[5];
    int tid = threadIdx.x;             // 256
    int wid = tid >> 5, lane = tid & 31;
    for (int it = 0; it < 4; it++) {
        int o = wid*32 + (it << 3) + (lane >> 2);
        float s = 0.f;
        for (int k = (lane & 3); k < 512; k += 4) s += g_FC[k]*w_out[(size_t)o*512 + k];
        s += __shfl_down_sync(0xffffffffu, s, 2);
        s += __shfl_down_sync(0xffffffffu, s, 1);
        if ((lane & 3) == 0) fc2[o] = sigm(s + b_out[o]);
    }
    __syncthreads();
    if (wid < 5) {
        float s = 0.f;
        for (int k = lane; k < 256; k += 32) s += fc2[k]*w_out1[wid*256 + k];
        for (int d = 16; d; d >>= 1) s += __shfl_down_sync(0xffffffffu, s, d);
        if (!lane) logit[wid] = s + b_out1[wid];
    }
    __syncthreads();
    if (tid == 0) {
        float mx = logit[0];
        for (int c=1;c<5;c++) mx = fmaxf(mx, logit[c]);
        float sum = 0.f;
        for (int c=0;c<5;c++) sum += expf(logit[c]-mx);
        float l = logf(sum);
        for (int c=0;c<5;c++) out[c] = logit[c] - mx - l;
    }
}

// ---------------- launch ----------------
extern "C" void kernel_launch(void* const* d_in, const int* in_sizes, int n_in,
                              void* d_out, int out_size)
{
    const int*   linputs    = (const int*)  d_in[0];
    const int*   rinputs    = (const int*)  d_in[1];
    const int*   child_idx  = (const int*)  d_in[2];
    const float* child_mask = (const float*)d_in[3];
    const float* emb        = (const float*)d_in[4];
    const float* w_ioux     = (const float*)d_in[5];
    const float* b_ioux     = (const float*)d_in[6];
    const float* w_iouh     = (const float*)d_in[7];
    const float* b_iouh     = (const float*)d_in[8];
    const float* w_fx       = (const float*)d_in[9];
    const float* b_fx       = (const float*)d_in[10];
    const float* w_fh       = (const float*)d_in[11];
    const float* b_fh       = (const float*)d_in[12];
    const float* ws1        = (const float*)d_in[13];
    const float* ws2        = (const float*)d_in[14];
    const float* wf         = (const float*)d_in[15];
    const float* w_lat      = (const float*)d_in[16];
    const float* b_lat      = (const float*)d_in[17];
    const float* w_fc       = (const float*)d_in[18];
    const float* b_fc       = (const float*)d_in[19];
    const float* w_out      = (const float*)d_in[20];
    const float* b_out      = (const float*)d_in[21];
    const float* w_out1     = (const float*)d_in[22];
    const float* b_out1     = (const float*)d_in[23];
    float* out = (float*)d_out;

    float *pH, *pHB, *pLOG, *pALPHA, *pM, *pLS;
    cudaGetSymbolAddress((void**)&pH,     g_H);
    cudaGetSymbolAddress((void**)&pHB,    g_HB);
    cudaGetSymbolAddress((void**)&pLOG,   g_LOG);
    cudaGetSymbolAddress((void**)&pALPHA, g_ALPHA);
    cudaGetSymbolAddress((void**)&pM,     g_Mm);
    cudaGetSymbolAddress((void**)&pLS,    g_LS);

    // 0) weight conversion to half (2,162,688 float4 groups)
    k_cvtW<<<8448, 256>>>(w_ioux, w_fx, w_iouh, w_fh, ws1);

    // 1) embedding gather (half)
    k_embed<<<1024, 256>>>(linputs, rinputs, emb);

    // 2) fused input projections: M=1024, N=4096, K=1024
    gemm_h<0><<<dim3(64, 8, 1), 256>>>(b_ioux, b_fx, nullptr, nullptr, 0, 0);

    // 3) leaves
    k_leaf<<<2048, 256>>>(b_iouh);

    // 4) internal levels (split-K=2 fp16 GEMM, then pointwise)
    for (int h = 1; h <= 15; h++) {
        int B = SCHED.cnt[h];
        if (B == 0) continue;
        int ny = (4*B + 127)/128; if (ny < 1) ny = 1;
        gemm_h<1><<<dim3(48, ny, 4), 256>>>(nullptr, nullptr,
                                            child_idx, child_mask, h, B);
        k_point<<<(2*B*1024 + 255)/256, 256>>>(child_idx, child_mask, h, B, b_iouh, b_fh);
    }

    // 5) attention
    gemm_h<2><<<dim3(4, 8, 1), 256>>>(nullptr, nullptr, nullptr, nullptr, 0, 0);
    gemm_s<true,0><<<dim3(1,16,1), 128>>>(pHB, ws2, nullptr, pLOG,
                                          1024, 16, 256, 0, 0, 0);
    k_soft<<<32, 512>>>(out);
    gemm_s<false,0><<<dim3(16,1,2), 128>>>(pALPHA, pH, nullptr, pM,
                                           16, 1024, 512, 16*512, 512*1024, 16*1024);

    // 6) head
    gemm_s<false,2><<<dim3(16,1,1), 128>>>(pM, wf, nullptr, pLS,
                                           32, 1024, 1024, 0, 0, 0);
    k_lat<<<4, 256>>>(w_lat, b_lat);
    k_fc<<<64, 256>>>(w_fc, b_fc);
    k_fc2out<<<1, 256>>>(w_out, b_out, w_out1, b_out1, out);
}